// round 12
// baseline (speedup 1.0000x reference)
#include <cuda_runtime.h>
#include <cuda_fp16.h>
#include <cstdint>
#include <math.h>

#define BATCH 2
#define SEQ   2048
#define DIM   4096
#define KV_DIM 1024
#define NHQ   32
#define NHK   8
#define HD    128
#define MROWS (BATCH*SEQ)

// scratch (no allocations allowed)
__device__ float g_q[MROWS*DIM];
__device__ float g_k[MROWS*KV_DIM];
__device__ float g_v[MROWS*KV_DIM];
__device__ __half g_hx[MROWS*DIM];
__device__ __half g_hwq[DIM*DIM];
__device__ __half g_hwk[KV_DIM*DIM];
__device__ __half g_hwv[KV_DIM*DIM];
__device__ __half g_hwo[DIM*DIM];
__device__ __half g_hq[MROWS*DIM];
__device__ __half g_hk[MROWS*KV_DIM];
__device__ __half g_hv[MROWS*KV_DIM];
__device__ __half g_ho[MROWS*DIM];   // attention output (fp16, wo input)

// ==================================================================
// helpers
// ==================================================================
__device__ __forceinline__ void ldsm4(uint32_t& r0, uint32_t& r1,
                                      uint32_t& r2, uint32_t& r3, uint32_t addr)
{
    asm volatile("ldmatrix.sync.aligned.m8n8.x4.shared.b16 {%0,%1,%2,%3}, [%4];"
                 : "=r"(r0), "=r"(r1), "=r"(r2), "=r"(r3) : "r"(addr));
}

__device__ __forceinline__ void ldsm4t(uint32_t& r0, uint32_t& r1,
                                       uint32_t& r2, uint32_t& r3, uint32_t addr)
{
    asm volatile("ldmatrix.sync.aligned.m8n8.x4.trans.shared.b16 {%0,%1,%2,%3}, [%4];"
                 : "=r"(r0), "=r"(r1), "=r"(r2), "=r"(r3) : "r"(addr));
}

__device__ __forceinline__ void mma_f16(float* d, const uint32_t* a,
                                        uint32_t b0, uint32_t b1)
{
    asm volatile("mma.sync.aligned.m16n8k16.row.col.f32.f16.f16.f32 "
                 "{%0,%1,%2,%3},{%4,%5,%6,%7},{%8,%9},{%0,%1,%2,%3};"
                 : "+f"(d[0]), "+f"(d[1]), "+f"(d[2]), "+f"(d[3])
                 : "r"(a[0]), "r"(a[1]), "r"(a[2]), "r"(a[3]),
                   "r"(b0), "r"(b1));
}

__device__ __forceinline__ void cp_async16(uint32_t dst, const void* src)
{
    asm volatile("cp.async.cg.shared.global [%0], [%1], 16;" :: "r"(dst), "l"(src));
}
__device__ __forceinline__ void cp_commit()
{
    asm volatile("cp.async.commit_group;");
}
template<int N> __device__ __forceinline__ void cp_wait()
{
    asm volatile("cp.async.wait_group %0;" :: "n"(N));
}

// ==================================================================
// conversion kernels
// ==================================================================
__global__ void to_half_kernel(const float* __restrict__ in,
                               __half* __restrict__ out, int n4)
{
    int i = blockIdx.x * blockDim.x + threadIdx.x;
    if (i < n4) {
        float4 v = ((const float4*)in)[i];
        ((__half2*)out)[i * 2]     = __floats2half2_rn(v.x, v.y);
        ((__half2*)out)[i * 2 + 1] = __floats2half2_rn(v.z, v.w);
    }
}

// ==================================================================
// FP16 GEMM (NT): C = A * B^T, fp32 accum.
// 128x128x64(halves) CTA tile, 128 threads = 4 warps (2Mx2N),
// warp tile 64x64 -> per k16: 8 ldsm, 32 MMA (ratio 4:1).
// 3-stage cp.async, 2 CTAs/SM. Optional z-fusion of two GEMMs.
// ==================================================================
#define HBM 128
#define HBN 128
#define HBK 64
#define HSTAGES 3
#define HSTAGE_BYTES 32768
#define HGEMM_SMEM (HSTAGES*HSTAGE_BYTES)

__global__ __launch_bounds__(128, 2)
void gemm_f16(const __half* __restrict__ A,
              const __half* __restrict__ B0, const __half* __restrict__ B1,
              float* __restrict__ C0, float* __restrict__ C1,
              int M, int N, int K)
{
    extern __shared__ char hsm[];
    const uint32_t su = (uint32_t)__cvta_generic_to_shared(hsm);

    const __half* B = blockIdx.z ? B1 : B0;
    float*        C = blockIdx.z ? C1 : C0;

    const int tid  = threadIdx.x;
    const int lane = tid & 31;
    const int warp = tid >> 5;
    const int wm   = warp & 1;
    const int wn   = warp >> 1;
    const int bm   = blockIdx.y;
    const int bn   = blockIdx.x;

    // loader: thread owns full 128B row of A and of B per stage
    const int lrow = tid;
    const int lsw  = lrow & 7;
    const __half* Ap = A + (long)(bm * HBM + lrow) * K;
    const __half* Bp = B + (long)(bn * HBN + lrow) * K;
    const uint32_t aDst = su + (uint32_t)(lrow * 128);
    const uint32_t bDst = aDst + 16384u;

    // fragment lane constants
    const int grp  = lane >> 3;
    const int lr   = lane & 7;
    const int frow = lr + 8 * (grp & 1);
    const int gk   = grp >> 1;

    float c[4][8][4];
    for (int mt = 0; mt < 4; mt++) {
        for (int nt = 0; nt < 8; nt++) {
            for (int r = 0; r < 4; r++) {
                c[mt][nt][r] = 0.f;
            }
        }
    }

    const int T = K / HBK;

    for (int s = 0; s < HSTAGES - 1; s++) {
        int k0 = s * HBK;
        uint32_t ad = aDst + (uint32_t)s * HSTAGE_BYTES;
        uint32_t bd = bDst + (uint32_t)s * HSTAGE_BYTES;
#pragma unroll
        for (int u = 0; u < 8; u++) {
            uint32_t so = (uint32_t)((u ^ lsw) << 4);
            cp_async16(ad + so, Ap + k0 + u * 8);
            cp_async16(bd + so, Bp + k0 + u * 8);
        }
        cp_commit();
    }

    for (int ks = 0; ks < T; ks++) {
        cp_wait<HSTAGES - 2>();
        __syncthreads();

        int nk = ks + HSTAGES - 1;
        if (nk < T) {
            int slot = nk % HSTAGES;
            int k0 = nk * HBK;
            uint32_t ad = aDst + (uint32_t)slot * HSTAGE_BYTES;
            uint32_t bd = bDst + (uint32_t)slot * HSTAGE_BYTES;
#pragma unroll
            for (int u = 0; u < 8; u++) {
                uint32_t so = (uint32_t)((u ^ lsw) << 4);
                cp_async16(ad + so, Ap + k0 + u * 8);
                cp_async16(bd + so, Bp + k0 + u * 8);
            }
            cp_commit();
        }

        const uint32_t Abase = su + (uint32_t)((ks % HSTAGES) * HSTAGE_BYTES);
        const uint32_t Bbase = Abase + 16384u;

#pragma unroll
        for (int kk = 0; kk < 4; kk++) {
            int u = kk * 2 + gk;
            uint32_t af[4][4];
#pragma unroll
            for (int mt = 0; mt < 4; mt++) {
                int row = wm * 64 + mt * 16 + frow;
                int uu  = u ^ (row & 7);
                ldsm4(af[mt][0], af[mt][1], af[mt][2], af[mt][3],
                      Abase + (uint32_t)(row * 128 + uu * 16));
            }
            uint32_t bf[4][4];
#pragma unroll
            for (int jp = 0; jp < 4; jp++) {
                int row = wn * 64 + jp * 16 + frow;
                int uu  = u ^ (row & 7);
                ldsm4(bf[jp][0], bf[jp][1], bf[jp][2], bf[jp][3],
                      Bbase + (uint32_t)(row * 128 + uu * 16));
            }
#pragma unroll
            for (int mt = 0; mt < 4; mt++) {
#pragma unroll
                for (int nt = 0; nt < 8; nt++) {
                    uint32_t b0 = bf[nt >> 1][nt & 1];
                    uint32_t b1 = bf[nt >> 1][(nt & 1) + 2];
                    mma_f16(c[mt][nt], af[mt], b0, b1);
                }
            }
        }
    }

    const int g  = lane >> 2;
    const int t2 = (lane & 3) * 2;
    for (int mt = 0; mt < 4; mt++) {
        int row0 = bm * HBM + wm * 64 + mt * 16 + g;
        for (int nt = 0; nt < 8; nt++) {
            int col = bn * HBN + wn * 64 + nt * 8 + t2;
            *(float2*)(C + (long)row0 * N + col)       = make_float2(c[mt][nt][0], c[mt][nt][1]);
            *(float2*)(C + (long)(row0 + 8) * N + col) = make_float2(c[mt][nt][2], c[mt][nt][3]);
        }
    }
}

// ==================================================================
// RoPE: fp32 math, writes fp16 (q pre-scaled by 1/sqrt(HD))
// ==================================================================
__global__ void rope_half_kernel(const float* __restrict__ src,
                                 __half* __restrict__ dst,
                                 const int* __restrict__ sp,
                                 int nh, int stride, float scale)
{
    int idx = blockIdx.x * blockDim.x + threadIdx.x;
    int i   = idx & 63;
    int h   = (idx >> 6) % nh;
    int row = idx / (64 * nh);
    int pos = (row % SEQ) + sp[0];

    float invf = (float)pow(10000.0, -(double)i / 64.0);
    float ang  = __fmul_rn((float)pos, invf);
    float sn;
    float cs;
    sincosf(ang, &sn, &cs);

    float2 v = ((const float2*)(src + (long)row * stride + h * HD))[i];
    float o0 = (v.x * cs - v.y * sn) * scale;
    float o1 = (v.x * sn + v.y * cs) * scale;
    ((__half2*)(dst + (long)row * stride + h * HD))[i] = __floats2half2_rn(o0, o1);
}

// ==================================================================
// FP16 flash attention (R10, proven) — epilogue now emits fp16
// ==================================================================
#define ASQ  0
#define ASK0 32768
#define ASK1 49152
#define ASV0 65536
#define ASV1 81920
#define ASPS 98304
#define ATTN_SMEM 114688

__global__ __launch_bounds__(256, 1)
void attn_f16_kernel(const __half* __restrict__ Q, const __half* __restrict__ Kg,
                     const __half* __restrict__ Vg, __half* __restrict__ O)
{
    extern __shared__ char smc[];
    const uint32_t su = (uint32_t)__cvta_generic_to_shared(smc);
    const int tid  = threadIdx.x;
    const int lane = tid & 31;
    const int warp = tid >> 5;
    const int qt = blockIdx.x;
    const int h  = blockIdx.y;
    const int b  = blockIdx.z;
    const int hk = h >> 2;
    const int q0 = qt * 128;

    const int grp  = lane >> 3;
    const int lr   = lane & 7;
    const int frow = lr + 8 * (grp & 1);
    const int gsel = grp >> 1;
    const int qrow = warp * 16 + frow;

    {
        int row = tid >> 1;
        int u0  = (tid & 1) * 8;
        const __half* src = Q + (long)(b * SEQ + q0 + row) * DIM + h * HD;
#pragma unroll
        for (int p = 0; p < 8; p++) {
            int u  = u0 + p;
            int uu = (u & 8) | ((u & 7) ^ (row & 7));
            cp_async16(su + ASQ + (uint32_t)(row * 256 + uu * 16), src + u * 8);
        }
        cp_commit();
    }

    const int lkrow = tid >> 2;
    const int lku   = tid & 3;
    auto load_kv = [&](int kt2, int bb2) {
        long roff = (long)(b * SEQ + kt2 * 64 + lkrow);
        const __half* ks = Kg + roff * KV_DIM + hk * HD;
        const __half* vs = Vg + roff * KV_DIM + hk * HD;
        uint32_t kd = su + (bb2 ? ASK1 : ASK0) + (uint32_t)(lkrow * 256);
        uint32_t vd = su + (bb2 ? ASV1 : ASV0) + (uint32_t)(lkrow * 256);
#pragma unroll
        for (int p = 0; p < 4; p++) {
            int u  = lku + p * 4;
            int uu = (u & 8) | ((u & 7) ^ (lkrow & 7));
            cp_async16(kd + (uint32_t)(uu * 16), ks + u * 8);
            cp_async16(vd + (uint32_t)(uu * 16), vs + u * 8);
        }
    };

    load_kv(0, 0);
    cp_commit();
    load_kv(1, 1);
    cp_commit();

    float oacc[16][4];
    for (int nt = 0; nt < 16; nt++) {
        for (int r = 0; r < 4; r++) {
            oacc[nt][r] = 0.f;
        }
    }
    float m0 = -1e30f, m1 = -1e30f, l0 = 0.f, l1 = 0.f;

    for (int kt = 0; kt < 32; kt++) {
        cp_wait<1>();
        __syncthreads();

        int bb = kt & 1;
        const uint32_t Kbase = su + (bb ? ASK1 : ASK0);
        const uint32_t Vbase = su + (bb ? ASV1 : ASV0);

        float sc[8][4];
        for (int nt = 0; nt < 8; nt++) {
            for (int r = 0; r < 4; r++) {
                sc[nt][r] = 0.f;
            }
        }
#pragma unroll
        for (int kk = 0; kk < 8; kk++) {
            int u = 2 * kk + gsel;
            uint32_t af[4];
            {
                int uu = (u & 8) | ((u & 7) ^ (qrow & 7));
                ldsm4(af[0], af[1], af[2], af[3],
                      su + ASQ + (uint32_t)(qrow * 256 + uu * 16));
            }
            uint32_t bf[4][4];
#pragma unroll
            for (int jp = 0; jp < 4; jp++) {
                int row = jp * 16 + frow;
                int uu  = (u & 8) | ((u & 7) ^ (row & 7));
                ldsm4(bf[jp][0], bf[jp][1], bf[jp][2], bf[jp][3],
                      Kbase + (uint32_t)(row * 256 + uu * 16));
            }
#pragma unroll
            for (int nt = 0; nt < 8; nt++) {
                mma_f16(sc[nt], af, bf[nt >> 1][nt & 1], bf[nt >> 1][(nt & 1) + 2]);
            }
        }

        {
            float mx0 = -1e30f, mx1 = -1e30f;
#pragma unroll
            for (int nt = 0; nt < 8; nt++) {
                mx0 = fmaxf(mx0, fmaxf(sc[nt][0], sc[nt][1]));
                mx1 = fmaxf(mx1, fmaxf(sc[nt][2], sc[nt][3]));
            }
            mx0 = fmaxf(mx0, __shfl_xor_sync(0xffffffffu, mx0, 1));
            mx0 = fmaxf(mx0, __shfl_xor_sync(0xffffffffu, mx0, 2));
            mx1 = fmaxf(mx1, __shfl_xor_sync(0xffffffffu, mx1, 1));
            mx1 = fmaxf(mx1, __shfl_xor_sync(0xffffffffu, mx1, 2));
            float nm0 = fmaxf(m0, mx0);
            float nm1 = fmaxf(m1, mx1);
            float cf0 = __expf(m0 - nm0);
            float cf1 = __expf(m1 - nm1);
            m0 = nm0;
            m1 = nm1;

            const int g  = lane >> 2;
            const int t2 = (lane & 3) * 2;
            const int prow0 = warp * 16 + g;
            const int prow1 = prow0 + 8;
            float ps0 = 0.f, ps1 = 0.f;
#pragma unroll
            for (int nt = 0; nt < 8; nt++) {
                float p0 = __expf(sc[nt][0] - nm0);
                float p1 = __expf(sc[nt][1] - nm0);
                float p2 = __expf(sc[nt][2] - nm1);
                float p3 = __expf(sc[nt][3] - nm1);
                ps0 += p0 + p1;
                ps1 += p2 + p3;
                __half2 h01 = __floats2half2_rn(p0, p1);
                __half2 h23 = __floats2half2_rn(p2, p3);
                int uu0 = nt ^ (prow0 & 7);
                int uu1 = nt ^ (prow1 & 7);
                *(__half2*)(smc + ASPS + prow0 * 128 + uu0 * 16 + t2 * 2) = h01;
                *(__half2*)(smc + ASPS + prow1 * 128 + uu1 * 16 + t2 * 2) = h23;
            }
            ps0 += __shfl_xor_sync(0xffffffffu, ps0, 1);
            ps0 += __shfl_xor_sync(0xffffffffu, ps0, 2);
            ps1 += __shfl_xor_sync(0xffffffffu, ps1, 1);
            ps1 += __shfl_xor_sync(0xffffffffu, ps1, 2);
            l0 = l0 * cf0 + ps0;
            l1 = l1 * cf1 + ps1;
#pragma unroll
            for (int nt = 0; nt < 16; nt++) {
                oacc[nt][0] *= cf0;
                oacc[nt][1] *= cf0;
                oacc[nt][2] *= cf1;
                oacc[nt][3] *= cf1;
            }
        }
        __syncwarp();

#pragma unroll
        for (int k2 = 0; k2 < 4; k2++) {
            uint32_t af[4];
            {
                int u  = 2 * k2 + gsel;
                int uu = u ^ (qrow & 7);
                ldsm4(af[0], af[1], af[2], af[3],
                      su + ASPS + (uint32_t)(qrow * 128 + uu * 16));
            }
            uint32_t vf[8][4];
#pragma unroll
            for (int jp = 0; jp < 8; jp++) {
                int row = k2 * 16 + frow;
                int u   = 2 * jp + gsel;
                int uu  = (u & 8) | ((u & 7) ^ (row & 7));
                ldsm4t(vf[jp][0], vf[jp][1], vf[jp][2], vf[jp][3],
                       Vbase + (uint32_t)(row * 256 + uu * 16));
            }
#pragma unroll
            for (int jp = 0; jp < 8; jp++) {
                mma_f16(oacc[jp * 2],     af, vf[jp][0], vf[jp][1]);
                mma_f16(oacc[jp * 2 + 1], af, vf[jp][2], vf[jp][3]);
            }
        }
        __syncthreads();

        if (kt + 2 < 32) {
            load_kv(kt + 2, bb);
        }
        cp_commit();
    }

    // epilogue — write fp16 directly (same rounding as store-f32 + convert)
    {
        float r0 = 1.f / l0;
        float r1 = 1.f / l1;
        const int g  = lane >> 2;
        const int t2 = (lane & 3) * 2;
        int row0 = q0 + warp * 16 + g;
        __half* op0 = O + (long)(b * SEQ + row0) * DIM + h * HD;
        __half* op1 = op0 + (long)8 * DIM;
#pragma unroll
        for (int nt = 0; nt < 16; nt++) {
            *(__half2*)(op0 + nt * 8 + t2) =
                __floats2half2_rn(oacc[nt][0] * r0, oacc[nt][1] * r0);
            *(__half2*)(op1 + nt * 8 + t2) =
                __floats2half2_rn(oacc[nt][2] * r1, oacc[nt][3] * r1);
        }
    }
}

// ==================================================================
// Launch
// ==================================================================
extern "C" void kernel_launch(void* const* d_in, const int* in_sizes, int n_in,
                              void* d_out, int out_size)
{
    (void)in_sizes;
    (void)n_in;
    (void)out_size;
    const float* x  = (const float*)d_in[0];
    const float* wq = (const float*)d_in[1];
    const float* wk = (const float*)d_in[2];
    const float* wv = (const float*)d_in[3];
    const float* wo = (const float*)d_in[4];
    const int*   sp = (const int*)d_in[5];
    float* out = (float*)d_out;

    float* q;
    float* k;
    float* v;
    __half* hx;
    __half* hwq;
    __half* hwk;
    __half* hwv;
    __half* hwo;
    __half* hq;
    __half* hkb;
    __half* hvb;
    __half* ho;
    cudaGetSymbolAddress((void**)&q,    g_q);
    cudaGetSymbolAddress((void**)&k,    g_k);
    cudaGetSymbolAddress((void**)&v,    g_v);
    cudaGetSymbolAddress((void**)&hx,   g_hx);
    cudaGetSymbolAddress((void**)&hwq,  g_hwq);
    cudaGetSymbolAddress((void**)&hwk,  g_hwk);
    cudaGetSymbolAddress((void**)&hwv,  g_hwv);
    cudaGetSymbolAddress((void**)&hwo,  g_hwo);
    cudaGetSymbolAddress((void**)&hq,   g_hq);
    cudaGetSymbolAddress((void**)&hkb,  g_hk);
    cudaGetSymbolAddress((void**)&hvb,  g_hv);
    cudaGetSymbolAddress((void**)&ho,   g_ho);

    cudaFuncSetAttribute(gemm_f16,
                         cudaFuncAttributeMaxDynamicSharedMemorySize, HGEMM_SMEM);
    cudaFuncSetAttribute(attn_f16_kernel,
                         cudaFuncAttributeMaxDynamicSharedMemorySize, ATTN_SMEM);

    {
        int n4x  = MROWS * DIM / 4;
        int n4q  = DIM * DIM / 4;
        int n4kv = KV_DIM * DIM / 4;
        to_half_kernel<<<(n4x  + 255) / 256, 256>>>(x,  hx,  n4x);
        to_half_kernel<<<(n4q  + 255) / 256, 256>>>(wq, hwq, n4q);
        to_half_kernel<<<(n4kv + 255) / 256, 256>>>(wk, hwk, n4kv);
        to_half_kernel<<<(n4kv + 255) / 256, 256>>>(wv, hwv, n4kv);
        to_half_kernel<<<(n4q  + 255) / 256, 256>>>(wo, hwo, n4q);
    }

    dim3 gq(DIM / HBN, MROWS / HBM, 1);       // (32, 32, 1)
    dim3 gkv(KV_DIM / HBN, MROWS / HBM, 2);   // (8, 32, 2) — k and v fused
    gemm_f16<<<gq,  128, HGEMM_SMEM>>>(hx, hwq, hwq, q, q, MROWS, DIM, DIM);
    gemm_f16<<<gkv, 128, HGEMM_SMEM>>>(hx, hwk, hwv, k, v, MROWS, KV_DIM, DIM);

    rope_half_kernel<<<(MROWS * NHQ * 64) / 256, 256>>>(q, hq, sp, NHQ, DIM,
                                                        0.08838834764831845f);
    rope_half_kernel<<<(MROWS * NHK * 64) / 256, 256>>>(k, hkb, sp, NHK, KV_DIM, 1.0f);
    {
        int n4v = MROWS * KV_DIM / 4;
        to_half_kernel<<<(n4v + 255) / 256, 256>>>(v, hvb, n4v);
    }

    dim3 ga(SEQ / 128, NHQ, BATCH);
    attn_f16_kernel<<<ga, 256, ATTN_SMEM>>>(hq, hkb, hvb, ho);

    gemm_f16<<<gq, 128, HGEMM_SMEM>>>(ho, hwo, hwo, out, out, MROWS, DIM, DIM);
}

// round 13
// speedup vs baseline: 1.1829x; 1.1829x over previous
#include <cuda_runtime.h>
#include <cuda_fp16.h>
#include <cstdint>
#include <math.h>

#define BATCH 2
#define SEQ   2048
#define DIM   4096
#define KV_DIM 1024
#define NHQ   32
#define NHK   8
#define HD    128
#define MROWS (BATCH*SEQ)

// scratch (no allocations allowed)
__device__ float g_q[MROWS*DIM];
__device__ float g_k[MROWS*KV_DIM];
__device__ float g_v[MROWS*KV_DIM];
__device__ __half g_hx[MROWS*DIM];
__device__ __half g_hwq[DIM*DIM];
__device__ __half g_hwk[KV_DIM*DIM];
__device__ __half g_hwv[KV_DIM*DIM];
__device__ __half g_hwo[DIM*DIM];
__device__ __half g_hq[MROWS*DIM];
__device__ __half g_hk[MROWS*KV_DIM];
__device__ __half g_hv[MROWS*KV_DIM];
__device__ __half g_ho[MROWS*DIM];

// ==================================================================
// helpers
// ==================================================================
__device__ __forceinline__ void ldsm4(uint32_t& r0, uint32_t& r1,
                                      uint32_t& r2, uint32_t& r3, uint32_t addr)
{
    asm volatile("ldmatrix.sync.aligned.m8n8.x4.shared.b16 {%0,%1,%2,%3}, [%4];"
                 : "=r"(r0), "=r"(r1), "=r"(r2), "=r"(r3) : "r"(addr));
}

__device__ __forceinline__ void ldsm4t(uint32_t& r0, uint32_t& r1,
                                       uint32_t& r2, uint32_t& r3, uint32_t addr)
{
    asm volatile("ldmatrix.sync.aligned.m8n8.x4.trans.shared.b16 {%0,%1,%2,%3}, [%4];"
                 : "=r"(r0), "=r"(r1), "=r"(r2), "=r"(r3) : "r"(addr));
}

__device__ __forceinline__ void mma_f16(float* d, const uint32_t* a,
                                        uint32_t b0, uint32_t b1)
{
    asm volatile("mma.sync.aligned.m16n8k16.row.col.f32.f16.f16.f32 "
                 "{%0,%1,%2,%3},{%4,%5,%6,%7},{%8,%9},{%0,%1,%2,%3};"
                 : "+f"(d[0]), "+f"(d[1]), "+f"(d[2]), "+f"(d[3])
                 : "r"(a[0]), "r"(a[1]), "r"(a[2]), "r"(a[3]),
                   "r"(b0), "r"(b1));
}

__device__ __forceinline__ void cp_async16(uint32_t dst, const void* src)
{
    asm volatile("cp.async.cg.shared.global [%0], [%1], 16;" :: "r"(dst), "l"(src));
}
__device__ __forceinline__ void cp_commit()
{
    asm volatile("cp.async.commit_group;");
}
template<int N> __device__ __forceinline__ void cp_wait()
{
    asm volatile("cp.async.wait_group %0;" :: "n"(N));
}

// ==================================================================
// conversion kernel
// ==================================================================
__global__ void to_half_kernel(const float* __restrict__ in,
                               __half* __restrict__ out, int n4)
{
    int i = blockIdx.x * blockDim.x + threadIdx.x;
    if (i < n4) {
        float4 v = ((const float4*)in)[i];
        ((__half2*)out)[i * 2]     = __floats2half2_rn(v.x, v.y);
        ((__half2*)out)[i * 2 + 1] = __floats2half2_rn(v.z, v.w);
    }
}

// ==================================================================
// FP16 GEMM (NT) — R10's proven core (256 thr, 8 warps 4Mx2N, 32x64
// warp tiles, 3-stage cp.async, 2 CTAs/SM) + z-fusion of two GEMMs.
// ==================================================================
#define HBM 128
#define HBN 128
#define HBK 64
#define HSTAGES 3
#define HSTAGE_BYTES 32768
#define HGEMM_SMEM (HSTAGES*HSTAGE_BYTES)

__global__ __launch_bounds__(256, 2)
void gemm_f16(const __half* __restrict__ A,
              const __half* __restrict__ B0, const __half* __restrict__ B1,
              float* __restrict__ C0, float* __restrict__ C1,
              int M, int N, int K)
{
    extern __shared__ char hsm[];
    const uint32_t su = (uint32_t)__cvta_generic_to_shared(hsm);

    const __half* B = blockIdx.z ? B1 : B0;
    float*        C = blockIdx.z ? C1 : C0;

    const int tid  = threadIdx.x;
    const int lane = tid & 31;
    const int warp = tid >> 5;
    const int wm   = warp & 3;
    const int wn   = warp >> 2;
    const int bm   = blockIdx.y;
    const int bn   = blockIdx.x;

    const int lrow = tid >> 1;
    const int lu0  = (tid & 1) * 4;
    const __half* Ap = A + (long)(bm * HBM + lrow) * K;
    const __half* Bp = B + (long)(bn * HBN + lrow) * K;
    const uint32_t aDst = su + (uint32_t)(lrow * 128);
    const uint32_t bDst = aDst + 16384u;
    const int lsw = lrow & 7;

    const int grp = lane >> 3;
    const int lr  = lane & 7;
    const int frow = lr + 8 * (grp & 1);
    const int gk   = grp >> 1;
    const int rowA = wm * 32 + frow;
    const int rowB = wn * 64 + frow;
    const int swA = rowA & 7;
    const int swB = rowB & 7;
    const uint32_t aRowOff = (uint32_t)rowA * 128u;
    const uint32_t bRowOff = (uint32_t)rowB * 128u;

    float c[2][8][4];
    for (int mt = 0; mt < 2; mt++) {
        for (int nt = 0; nt < 8; nt++) {
            for (int r = 0; r < 4; r++) {
                c[mt][nt][r] = 0.f;
            }
        }
    }

    const int T = K / HBK;

    for (int s = 0; s < HSTAGES - 1; s++) {
        int k0 = s * HBK;
        uint32_t ad = aDst + (uint32_t)s * HSTAGE_BYTES;
        uint32_t bd = bDst + (uint32_t)s * HSTAGE_BYTES;
#pragma unroll
        for (int p = 0; p < 4; p++) {
            int u = lu0 + p;
            uint32_t so = (uint32_t)((u ^ lsw) << 4);
            cp_async16(ad + so, Ap + k0 + u * 8);
            cp_async16(bd + so, Bp + k0 + u * 8);
        }
        cp_commit();
    }

    for (int ks = 0; ks < T; ks++) {
        cp_wait<HSTAGES - 2>();
        __syncthreads();

        int nk = ks + HSTAGES - 1;
        if (nk < T) {
            int slot = nk % HSTAGES;
            int k0 = nk * HBK;
            uint32_t ad = aDst + (uint32_t)slot * HSTAGE_BYTES;
            uint32_t bd = bDst + (uint32_t)slot * HSTAGE_BYTES;
#pragma unroll
            for (int p = 0; p < 4; p++) {
                int u = lu0 + p;
                uint32_t so = (uint32_t)((u ^ lsw) << 4);
                cp_async16(ad + so, Ap + k0 + u * 8);
                cp_async16(bd + so, Bp + k0 + u * 8);
            }
            cp_commit();
        }

        const uint32_t Abase = su + (uint32_t)((ks % HSTAGES) * HSTAGE_BYTES);
        const uint32_t Bbase = Abase + 16384u;

#pragma unroll
        for (int kk = 0; kk < 4; kk++) {
            int u = kk * 2 + gk;
            uint32_t af0[4];
            uint32_t af1[4];
            uint32_t aAddr = Abase + aRowOff + (uint32_t)(((u ^ swA) & 7) << 4) +
                             (uint32_t)((u & 8) << 4);
            ldsm4(af0[0], af0[1], af0[2], af0[3], aAddr);
            ldsm4(af1[0], af1[1], af1[2], af1[3], aAddr + 2048u);

            uint32_t bf[4][4];
#pragma unroll
            for (int jp = 0; jp < 4; jp++) {
                uint32_t bAddr = Bbase + bRowOff + (uint32_t)(jp * 2048) +
                                 (uint32_t)(((u ^ swB) & 7) << 4) +
                                 (uint32_t)((u & 8) << 4);
                ldsm4(bf[jp][0], bf[jp][1], bf[jp][2], bf[jp][3], bAddr);
            }

#pragma unroll
            for (int nt = 0; nt < 8; nt++) {
                uint32_t b0 = bf[nt >> 1][nt & 1];
                uint32_t b1 = bf[nt >> 1][(nt & 1) + 2];
                mma_f16(c[0][nt], af0, b0, b1);
                mma_f16(c[1][nt], af1, b0, b1);
            }
        }
    }

    const int g  = lane >> 2;
    const int t2 = (lane & 3) * 2;
    for (int mt = 0; mt < 2; mt++) {
        int row0 = bm * HBM + wm * 32 + mt * 16 + g;
        for (int nt = 0; nt < 8; nt++) {
            int col = bn * HBN + wn * 64 + nt * 8 + t2;
            *(float2*)(C + (long)row0 * N + col)       = make_float2(c[mt][nt][0], c[mt][nt][1]);
            *(float2*)(C + (long)(row0 + 8) * N + col) = make_float2(c[mt][nt][2], c[mt][nt][3]);
        }
    }
}

// ==================================================================
// RoPE: fp32 math, writes fp16 (q pre-scaled by 1/sqrt(HD))
// ==================================================================
__global__ void rope_half_kernel(const float* __restrict__ src,
                                 __half* __restrict__ dst,
                                 const int* __restrict__ sp,
                                 int nh, int stride, float scale)
{
    int idx = blockIdx.x * blockDim.x + threadIdx.x;
    int i   = idx & 63;
    int h   = (idx >> 6) % nh;
    int row = idx / (64 * nh);
    int pos = (row % SEQ) + sp[0];

    float invf = (float)pow(10000.0, -(double)i / 64.0);
    float ang  = __fmul_rn((float)pos, invf);
    float sn;
    float cs;
    sincosf(ang, &sn, &cs);

    float2 v = ((const float2*)(src + (long)row * stride + h * HD))[i];
    float o0 = (v.x * cs - v.y * sn) * scale;
    float o1 = (v.x * sn + v.y * cs) * scale;
    ((__half2*)(dst + (long)row * stride + h * HD))[i] = __floats2half2_rn(o0, o1);
}

// ==================================================================
// FP16 flash attention (R10 core, fp16 direct-store epilogue)
// ==================================================================
#define ASQ  0
#define ASK0 32768
#define ASK1 49152
#define ASV0 65536
#define ASV1 81920
#define ASPS 98304
#define ATTN_SMEM 114688

__global__ __launch_bounds__(256, 1)
void attn_f16_kernel(const __half* __restrict__ Q, const __half* __restrict__ Kg,
                     const __half* __restrict__ Vg, __half* __restrict__ O)
{
    extern __shared__ char smc[];
    const uint32_t su = (uint32_t)__cvta_generic_to_shared(smc);
    const int tid  = threadIdx.x;
    const int lane = tid & 31;
    const int warp = tid >> 5;
    const int qt = blockIdx.x;
    const int h  = blockIdx.y;
    const int b  = blockIdx.z;
    const int hk = h >> 2;
    const int q0 = qt * 128;

    const int grp  = lane >> 3;
    const int lr   = lane & 7;
    const int frow = lr + 8 * (grp & 1);
    const int gsel = grp >> 1;
    const int qrow = warp * 16 + frow;

    {
        int row = tid >> 1;
        int u0  = (tid & 1) * 8;
        const __half* src = Q + (long)(b * SEQ + q0 + row) * DIM + h * HD;
#pragma unroll
        for (int p = 0; p < 8; p++) {
            int u  = u0 + p;
            int uu = (u & 8) | ((u & 7) ^ (row & 7));
            cp_async16(su + ASQ + (uint32_t)(row * 256 + uu * 16), src + u * 8);
        }
        cp_commit();
    }

    const int lkrow = tid >> 2;
    const int lku   = tid & 3;
    auto load_kv = [&](int kt2, int bb2) {
        long roff = (long)(b * SEQ + kt2 * 64 + lkrow);
        const __half* ks = Kg + roff * KV_DIM + hk * HD;
        const __half* vs = Vg + roff * KV_DIM + hk * HD;
        uint32_t kd = su + (bb2 ? ASK1 : ASK0) + (uint32_t)(lkrow * 256);
        uint32_t vd = su + (bb2 ? ASV1 : ASV0) + (uint32_t)(lkrow * 256);
#pragma unroll
        for (int p = 0; p < 4; p++) {
            int u  = lku + p * 4;
            int uu = (u & 8) | ((u & 7) ^ (lkrow & 7));
            cp_async16(kd + (uint32_t)(uu * 16), ks + u * 8);
            cp_async16(vd + (uint32_t)(uu * 16), vs + u * 8);
        }
    };

    load_kv(0, 0);
    cp_commit();
    load_kv(1, 1);
    cp_commit();

    float oacc[16][4];
    for (int nt = 0; nt < 16; nt++) {
        for (int r = 0; r < 4; r++) {
            oacc[nt][r] = 0.f;
        }
    }
    float m0 = -1e30f, m1 = -1e30f, l0 = 0.f, l1 = 0.f;

    for (int kt = 0; kt < 32; kt++) {
        cp_wait<1>();
        __syncthreads();

        int bb = kt & 1;
        const uint32_t Kbase = su + (bb ? ASK1 : ASK0);
        const uint32_t Vbase = su + (bb ? ASV1 : ASV0);

        float sc[8][4];
        for (int nt = 0; nt < 8; nt++) {
            for (int r = 0; r < 4; r++) {
                sc[nt][r] = 0.f;
            }
        }
#pragma unroll
        for (int kk = 0; kk < 8; kk++) {
            int u = 2 * kk + gsel;
            uint32_t af[4];
            {
                int uu = (u & 8) | ((u & 7) ^ (qrow & 7));
                ldsm4(af[0], af[1], af[2], af[3],
                      su + ASQ + (uint32_t)(qrow * 256 + uu * 16));
            }
            uint32_t bf[4][4];
#pragma unroll
            for (int jp = 0; jp < 4; jp++) {
                int row = jp * 16 + frow;
                int uu  = (u & 8) | ((u & 7) ^ (row & 7));
                ldsm4(bf[jp][0], bf[jp][1], bf[jp][2], bf[jp][3],
                      Kbase + (uint32_t)(row * 256 + uu * 16));
            }
#pragma unroll
            for (int nt = 0; nt < 8; nt++) {
                mma_f16(sc[nt], af, bf[nt >> 1][nt & 1], bf[nt >> 1][(nt & 1) + 2]);
            }
        }

        {
            float mx0 = -1e30f, mx1 = -1e30f;
#pragma unroll
            for (int nt = 0; nt < 8; nt++) {
                mx0 = fmaxf(mx0, fmaxf(sc[nt][0], sc[nt][1]));
                mx1 = fmaxf(mx1, fmaxf(sc[nt][2], sc[nt][3]));
            }
            mx0 = fmaxf(mx0, __shfl_xor_sync(0xffffffffu, mx0, 1));
            mx0 = fmaxf(mx0, __shfl_xor_sync(0xffffffffu, mx0, 2));
            mx1 = fmaxf(mx1, __shfl_xor_sync(0xffffffffu, mx1, 1));
            mx1 = fmaxf(mx1, __shfl_xor_sync(0xffffffffu, mx1, 2));
            float nm0 = fmaxf(m0, mx0);
            float nm1 = fmaxf(m1, mx1);
            float cf0 = __expf(m0 - nm0);
            float cf1 = __expf(m1 - nm1);
            m0 = nm0;
            m1 = nm1;

            const int g  = lane >> 2;
            const int t2 = (lane & 3) * 2;
            const int prow0 = warp * 16 + g;
            const int prow1 = prow0 + 8;
            float ps0 = 0.f, ps1 = 0.f;
#pragma unroll
            for (int nt = 0; nt < 8; nt++) {
                float p0 = __expf(sc[nt][0] - nm0);
                float p1 = __expf(sc[nt][1] - nm0);
                float p2 = __expf(sc[nt][2] - nm1);
                float p3 = __expf(sc[nt][3] - nm1);
                ps0 += p0 + p1;
                ps1 += p2 + p3;
                __half2 h01 = __floats2half2_rn(p0, p1);
                __half2 h23 = __floats2half2_rn(p2, p3);
                int uu0 = nt ^ (prow0 & 7);
                int uu1 = nt ^ (prow1 & 7);
                *(__half2*)(smc + ASPS + prow0 * 128 + uu0 * 16 + t2 * 2) = h01;
                *(__half2*)(smc + ASPS + prow1 * 128 + uu1 * 16 + t2 * 2) = h23;
            }
            ps0 += __shfl_xor_sync(0xffffffffu, ps0, 1);
            ps0 += __shfl_xor_sync(0xffffffffu, ps0, 2);
            ps1 += __shfl_xor_sync(0xffffffffu, ps1, 1);
            ps1 += __shfl_xor_sync(0xffffffffu, ps1, 2);
            l0 = l0 * cf0 + ps0;
            l1 = l1 * cf1 + ps1;
#pragma unroll
            for (int nt = 0; nt < 16; nt++) {
                oacc[nt][0] *= cf0;
                oacc[nt][1] *= cf0;
                oacc[nt][2] *= cf1;
                oacc[nt][3] *= cf1;
            }
        }
        __syncwarp();

#pragma unroll
        for (int k2 = 0; k2 < 4; k2++) {
            uint32_t af[4];
            {
                int u  = 2 * k2 + gsel;
                int uu = u ^ (qrow & 7);
                ldsm4(af[0], af[1], af[2], af[3],
                      su + ASPS + (uint32_t)(qrow * 128 + uu * 16));
            }
            uint32_t vf[8][4];
#pragma unroll
            for (int jp = 0; jp < 8; jp++) {
                int row = k2 * 16 + frow;
                int u   = 2 * jp + gsel;
                int uu  = (u & 8) | ((u & 7) ^ (row & 7));
                ldsm4t(vf[jp][0], vf[jp][1], vf[jp][2], vf[jp][3],
                       Vbase + (uint32_t)(row * 256 + uu * 16));
            }
#pragma unroll
            for (int jp = 0; jp < 8; jp++) {
                mma_f16(oacc[jp * 2],     af, vf[jp][0], vf[jp][1]);
                mma_f16(oacc[jp * 2 + 1], af, vf[jp][2], vf[jp][3]);
            }
        }
        __syncthreads();

        if (kt + 2 < 32) {
            load_kv(kt + 2, bb);
        }
        cp_commit();
    }

    {
        float r0 = 1.f / l0;
        float r1 = 1.f / l1;
        const int g  = lane >> 2;
        const int t2 = (lane & 3) * 2;
        int row0 = q0 + warp * 16 + g;
        __half* op0 = O + (long)(b * SEQ + row0) * DIM + h * HD;
        __half* op1 = op0 + (long)8 * DIM;
#pragma unroll
        for (int nt = 0; nt < 16; nt++) {
            *(__half2*)(op0 + nt * 8 + t2) =
                __floats2half2_rn(oacc[nt][0] * r0, oacc[nt][1] * r0);
            *(__half2*)(op1 + nt * 8 + t2) =
                __floats2half2_rn(oacc[nt][2] * r1, oacc[nt][3] * r1);
        }
    }
}

// ==================================================================
// Launch
// ==================================================================
extern "C" void kernel_launch(void* const* d_in, const int* in_sizes, int n_in,
                              void* d_out, int out_size)
{
    (void)in_sizes;
    (void)n_in;
    (void)out_size;
    const float* x  = (const float*)d_in[0];
    const float* wq = (const float*)d_in[1];
    const float* wk = (const float*)d_in[2];
    const float* wv = (const float*)d_in[3];
    const float* wo = (const float*)d_in[4];
    const int*   sp = (const int*)d_in[5];
    float* out = (float*)d_out;

    float* q;
    float* k;
    float* v;
    __half* hx;
    __half* hwq;
    __half* hwk;
    __half* hwv;
    __half* hwo;
    __half* hq;
    __half* hkb;
    __half* hvb;
    __half* ho;
    cudaGetSymbolAddress((void**)&q,    g_q);
    cudaGetSymbolAddress((void**)&k,    g_k);
    cudaGetSymbolAddress((void**)&v,    g_v);
    cudaGetSymbolAddress((void**)&hx,   g_hx);
    cudaGetSymbolAddress((void**)&hwq,  g_hwq);
    cudaGetSymbolAddress((void**)&hwk,  g_hwk);
    cudaGetSymbolAddress((void**)&hwv,  g_hwv);
    cudaGetSymbolAddress((void**)&hwo,  g_hwo);
    cudaGetSymbolAddress((void**)&hq,   g_hq);
    cudaGetSymbolAddress((void**)&hkb,  g_hk);
    cudaGetSymbolAddress((void**)&hvb,  g_hv);
    cudaGetSymbolAddress((void**)&ho,   g_ho);

    cudaFuncSetAttribute(gemm_f16,
                         cudaFuncAttributeMaxDynamicSharedMemorySize, HGEMM_SMEM);
    cudaFuncSetAttribute(attn_f16_kernel,
                         cudaFuncAttributeMaxDynamicSharedMemorySize, ATTN_SMEM);

    {
        int n4x  = MROWS * DIM / 4;
        int n4q  = DIM * DIM / 4;
        int n4kv = KV_DIM * DIM / 4;
        to_half_kernel<<<(n4x  + 255) / 256, 256>>>(x,  hx,  n4x);
        to_half_kernel<<<(n4q  + 255) / 256, 256>>>(wq, hwq, n4q);
        to_half_kernel<<<(n4kv + 255) / 256, 256>>>(wk, hwk, n4kv);
        to_half_kernel<<<(n4kv + 255) / 256, 256>>>(wv, hwv, n4kv);
        to_half_kernel<<<(n4q  + 255) / 256, 256>>>(wo, hwo, n4q);
    }

    dim3 gq(DIM / HBN, MROWS / HBM, 1);       // (32, 32, 1)
    dim3 gkv(KV_DIM / HBN, MROWS / HBM, 2);   // (8, 32, 2) — k and v fused
    gemm_f16<<<gq,  256, HGEMM_SMEM>>>(hx, hwq, hwq, q, q, MROWS, DIM, DIM);
    gemm_f16<<<gkv, 256, HGEMM_SMEM>>>(hx, hwk, hwv, k, v, MROWS, KV_DIM, DIM);

    rope_half_kernel<<<(MROWS * NHQ * 64) / 256, 256>>>(q, hq, sp, NHQ, DIM,
                                                        0.08838834764831845f);
    rope_half_kernel<<<(MROWS * NHK * 64) / 256, 256>>>(k, hkb, sp, NHK, KV_DIM, 1.0f);
    {
        int n4v = MROWS * KV_DIM / 4;
        to_half_kernel<<<(n4v + 255) / 256, 256>>>(v, hvb, n4v);
    }

    dim3 ga(SEQ / 128, NHQ, BATCH);
    attn_f16_kernel<<<ga, 256, ATTN_SMEM>>>(hq, hkb, hvb, ho);

    gemm_f16<<<gq, 256, HGEMM_SMEM>>>(ho, hwo, hwo, out, out, MROWS, DIM, DIM);
}

// round 14
// speedup vs baseline: 1.1908x; 1.0066x over previous
#include <cuda_runtime.h>
#include <cuda_fp16.h>
#include <cstdint>
#include <math.h>

#define BATCH 2
#define SEQ   2048
#define DIM   4096
#define KV_DIM 1024
#define NHQ   32
#define NHK   8
#define HD    128
#define MROWS (BATCH*SEQ)

// scratch (no allocations allowed)
__device__ float g_q[MROWS*DIM];
__device__ float g_k[MROWS*KV_DIM];
__device__ float g_v[MROWS*KV_DIM];
__device__ __half g_hx[MROWS*DIM];
__device__ __half g_hwq[DIM*DIM];
__device__ __half g_hwk[KV_DIM*DIM];
__device__ __half g_hwv[KV_DIM*DIM];
__device__ __half g_hwo[DIM*DIM];
__device__ __half g_hq[MROWS*DIM];
__device__ __half g_hk[MROWS*KV_DIM];
__device__ __half g_hv[MROWS*KV_DIM];
__device__ __half g_ho[MROWS*DIM];

// ==================================================================
// helpers
// ==================================================================
__device__ __forceinline__ void ldsm4(uint32_t& r0, uint32_t& r1,
                                      uint32_t& r2, uint32_t& r3, uint32_t addr)
{
    asm volatile("ldmatrix.sync.aligned.m8n8.x4.shared.b16 {%0,%1,%2,%3}, [%4];"
                 : "=r"(r0), "=r"(r1), "=r"(r2), "=r"(r3) : "r"(addr));
}

__device__ __forceinline__ void ldsm4t(uint32_t& r0, uint32_t& r1,
                                       uint32_t& r2, uint32_t& r3, uint32_t addr)
{
    asm volatile("ldmatrix.sync.aligned.m8n8.x4.trans.shared.b16 {%0,%1,%2,%3}, [%4];"
                 : "=r"(r0), "=r"(r1), "=r"(r2), "=r"(r3) : "r"(addr));
}

__device__ __forceinline__ void mma_f16(float* d, const uint32_t* a,
                                        uint32_t b0, uint32_t b1)
{
    asm volatile("mma.sync.aligned.m16n8k16.row.col.f32.f16.f16.f32 "
                 "{%0,%1,%2,%3},{%4,%5,%6,%7},{%8,%9},{%0,%1,%2,%3};"
                 : "+f"(d[0]), "+f"(d[1]), "+f"(d[2]), "+f"(d[3])
                 : "r"(a[0]), "r"(a[1]), "r"(a[2]), "r"(a[3]),
                   "r"(b0), "r"(b1));
}

__device__ __forceinline__ void cp_async16(uint32_t dst, const void* src)
{
    asm volatile("cp.async.cg.shared.global [%0], [%1], 16;" :: "r"(dst), "l"(src));
}
__device__ __forceinline__ void cp_commit()
{
    asm volatile("cp.async.commit_group;");
}
template<int N> __device__ __forceinline__ void cp_wait()
{
    asm volatile("cp.async.wait_group %0;" :: "n"(N));
}

// ==================================================================
// conversion kernels
// ==================================================================
__global__ void to_half_kernel(const float* __restrict__ in,
                               __half* __restrict__ out, int n4)
{
    int i = blockIdx.x * blockDim.x + threadIdx.x;
    if (i < n4) {
        float4 v = ((const float4*)in)[i];
        ((__half2*)out)[i * 2]     = __floats2half2_rn(v.x, v.y);
        ((__half2*)out)[i * 2 + 1] = __floats2half2_rn(v.z, v.w);
    }
}

// all 5 input conversions in one launch (range-decoded)
__global__ void to_half5_kernel(const float* s0, __half* d0, int n0,
                                const float* s1, __half* d1, int n1,
                                const float* s2, __half* d2, int n2,
                                const float* s3, __half* d3, int n3,
                                const float* s4, __half* d4, int n4)
{
    int j = blockIdx.x * blockDim.x + threadIdx.x;
    const float* in;
    __half* out;
    if (j < n0) { in = s0; out = d0; }
    else {
        j -= n0;
        if (j < n1) { in = s1; out = d1; }
        else {
            j -= n1;
            if (j < n2) { in = s2; out = d2; }
            else {
                j -= n2;
                if (j < n3) { in = s3; out = d3; }
                else {
                    j -= n3;
                    if (j >= n4) { return; }
                    in = s4; out = d4;
                }
            }
        }
    }
    float4 v = ((const float4*)in)[j];
    ((__half2*)out)[j * 2]     = __floats2half2_rn(v.x, v.y);
    ((__half2*)out)[j * 2 + 1] = __floats2half2_rn(v.z, v.w);
}

// ==================================================================
// FP16 GEMM body (R10/R13 proven core): 128x128x64 tile, 256 thr,
// 8 warps (4Mx2N, 32x64 warp tile), 3-stage cp.async, fp32 accum.
// ==================================================================
#define HBM 128
#define HBN 128
#define HBK 64
#define HSTAGES 3
#define HSTAGE_BYTES 32768
#define HGEMM_SMEM (HSTAGES*HSTAGE_BYTES)

__device__ __forceinline__ void gemm_body(const __half* __restrict__ A,
                                          const __half* __restrict__ B,
                                          float* __restrict__ C,
                                          int N, int K, int bm, int bn,
                                          char* hsm)
{
    const uint32_t su = (uint32_t)__cvta_generic_to_shared(hsm);

    const int tid  = threadIdx.x;
    const int lane = tid & 31;
    const int warp = tid >> 5;
    const int wm   = warp & 3;
    const int wn   = warp >> 2;

    const int lrow = tid >> 1;
    const int lu0  = (tid & 1) * 4;
    const __half* Ap = A + (long)(bm * HBM + lrow) * K;
    const __half* Bp = B + (long)(bn * HBN + lrow) * K;
    const uint32_t aDst = su + (uint32_t)(lrow * 128);
    const uint32_t bDst = aDst + 16384u;
    const int lsw = lrow & 7;

    const int grp = lane >> 3;
    const int lr  = lane & 7;
    const int frow = lr + 8 * (grp & 1);
    const int gk   = grp >> 1;
    const int rowA = wm * 32 + frow;
    const int rowB = wn * 64 + frow;
    const int swA = rowA & 7;
    const int swB = rowB & 7;
    const uint32_t aRowOff = (uint32_t)rowA * 128u;
    const uint32_t bRowOff = (uint32_t)rowB * 128u;

    float c[2][8][4];
    for (int mt = 0; mt < 2; mt++) {
        for (int nt = 0; nt < 8; nt++) {
            for (int r = 0; r < 4; r++) {
                c[mt][nt][r] = 0.f;
            }
        }
    }

    const int T = K / HBK;

    for (int s = 0; s < HSTAGES - 1; s++) {
        int k0 = s * HBK;
        uint32_t ad = aDst + (uint32_t)s * HSTAGE_BYTES;
        uint32_t bd = bDst + (uint32_t)s * HSTAGE_BYTES;
#pragma unroll
        for (int p = 0; p < 4; p++) {
            int u = lu0 + p;
            uint32_t so = (uint32_t)((u ^ lsw) << 4);
            cp_async16(ad + so, Ap + k0 + u * 8);
            cp_async16(bd + so, Bp + k0 + u * 8);
        }
        cp_commit();
    }

    for (int ks = 0; ks < T; ks++) {
        cp_wait<HSTAGES - 2>();
        __syncthreads();

        int nk = ks + HSTAGES - 1;
        if (nk < T) {
            int slot = nk % HSTAGES;
            int k0 = nk * HBK;
            uint32_t ad = aDst + (uint32_t)slot * HSTAGE_BYTES;
            uint32_t bd = bDst + (uint32_t)slot * HSTAGE_BYTES;
#pragma unroll
            for (int p = 0; p < 4; p++) {
                int u = lu0 + p;
                uint32_t so = (uint32_t)((u ^ lsw) << 4);
                cp_async16(ad + so, Ap + k0 + u * 8);
                cp_async16(bd + so, Bp + k0 + u * 8);
            }
            cp_commit();
        }

        const uint32_t Abase = su + (uint32_t)((ks % HSTAGES) * HSTAGE_BYTES);
        const uint32_t Bbase = Abase + 16384u;

#pragma unroll
        for (int kk = 0; kk < 4; kk++) {
            int u = kk * 2 + gk;
            uint32_t af0[4];
            uint32_t af1[4];
            uint32_t aAddr = Abase + aRowOff + (uint32_t)(((u ^ swA) & 7) << 4) +
                             (uint32_t)((u & 8) << 4);
            ldsm4(af0[0], af0[1], af0[2], af0[3], aAddr);
            ldsm4(af1[0], af1[1], af1[2], af1[3], aAddr + 2048u);

            uint32_t bf[4][4];
#pragma unroll
            for (int jp = 0; jp < 4; jp++) {
                uint32_t bAddr = Bbase + bRowOff + (uint32_t)(jp * 2048) +
                                 (uint32_t)(((u ^ swB) & 7) << 4) +
                                 (uint32_t)((u & 8) << 4);
                ldsm4(bf[jp][0], bf[jp][1], bf[jp][2], bf[jp][3], bAddr);
            }

#pragma unroll
            for (int nt = 0; nt < 8; nt++) {
                uint32_t b0 = bf[nt >> 1][nt & 1];
                uint32_t b1 = bf[nt >> 1][(nt & 1) + 2];
                mma_f16(c[0][nt], af0, b0, b1);
                mma_f16(c[1][nt], af1, b0, b1);
            }
        }
    }

    const int g  = lane >> 2;
    const int t2 = (lane & 3) * 2;
    for (int mt = 0; mt < 2; mt++) {
        int row0 = bm * HBM + wm * 32 + mt * 16 + g;
        for (int nt = 0; nt < 8; nt++) {
            int col = bn * HBN + wn * 64 + nt * 8 + t2;
            *(float2*)(C + (long)row0 * N + col)       = make_float2(c[mt][nt][0], c[mt][nt][1]);
            *(float2*)(C + (long)(row0 + 8) * N + col) = make_float2(c[mt][nt][2], c[mt][nt][3]);
        }
    }
}

// fused Q+K+V projections: flat 1536-CTA grid
// idx [0,1024): Q tiles (bn=idx&31, bm=idx>>5)
// idx [1024,1280): K tiles; [1280,1536): V tiles (bn=r&7, bm=r>>3)
__global__ __launch_bounds__(256, 2)
void gemm_qkv(const __half* __restrict__ hx,
              const __half* __restrict__ hwq,
              const __half* __restrict__ hwk,
              const __half* __restrict__ hwv,
              float* __restrict__ q, float* __restrict__ k, float* __restrict__ v)
{
    extern __shared__ char hsm[];
    int idx = blockIdx.x;
    const __half* B;
    float* C;
    int N;
    int bm;
    int bn;
    if (idx < 1024) {
        B = hwq; C = q; N = DIM;
        bn = idx & 31; bm = idx >> 5;
    } else {
        int t = idx - 1024;
        if (t < 256) { B = hwk; C = k; }
        else { B = hwv; C = v; t -= 256; }
        N = KV_DIM;
        bn = t & 7; bm = t >> 3;
    }
    gemm_body(hx, B, C, N, DIM, bm, bn, hsm);
}

// single GEMM (wo): C = A * B^T
__global__ __launch_bounds__(256, 2)
void gemm_wo(const __half* __restrict__ A, const __half* __restrict__ B,
             float* __restrict__ C, int N, int K)
{
    extern __shared__ char hsm[];
    gemm_body(A, B, C, N, K, blockIdx.y, blockIdx.x, hsm);
}

// ==================================================================
// RoPE: fp32 math, writes fp16 (q pre-scaled by 1/sqrt(HD))
// ==================================================================
__global__ void rope_half_kernel(const float* __restrict__ src,
                                 __half* __restrict__ dst,
                                 const int* __restrict__ sp,
                                 int nh, int stride, float scale)
{
    int idx = blockIdx.x * blockDim.x + threadIdx.x;
    int i   = idx & 63;
    int h   = (idx >> 6) % nh;
    int row = idx / (64 * nh);
    int pos = (row % SEQ) + sp[0];

    float invf = (float)pow(10000.0, -(double)i / 64.0);
    float ang  = __fmul_rn((float)pos, invf);
    float sn;
    float cs;
    sincosf(ang, &sn, &cs);

    float2 v = ((const float2*)(src + (long)row * stride + h * HD))[i];
    float o0 = (v.x * cs - v.y * sn) * scale;
    float o1 = (v.x * sn + v.y * cs) * scale;
    ((__half2*)(dst + (long)row * stride + h * HD))[i] = __floats2half2_rn(o0, o1);
}

// ==================================================================
// FP16 flash attention (R13 core) — now 2 CTAs/SM
// ==================================================================
#define ASQ  0
#define ASK0 32768
#define ASK1 49152
#define ASV0 65536
#define ASV1 81920
#define ASPS 98304
#define ATTN_SMEM 114688

__global__ __launch_bounds__(256, 2)
void attn_f16_kernel(const __half* __restrict__ Q, const __half* __restrict__ Kg,
                     const __half* __restrict__ Vg, __half* __restrict__ O)
{
    extern __shared__ char smc[];
    const uint32_t su = (uint32_t)__cvta_generic_to_shared(smc);
    const int tid  = threadIdx.x;
    const int lane = tid & 31;
    const int warp = tid >> 5;
    const int qt = blockIdx.x;
    const int h  = blockIdx.y;
    const int b  = blockIdx.z;
    const int hk = h >> 2;
    const int q0 = qt * 128;

    const int grp  = lane >> 3;
    const int lr   = lane & 7;
    const int frow = lr + 8 * (grp & 1);
    const int gsel = grp >> 1;
    const int qrow = warp * 16 + frow;

    {
        int row = tid >> 1;
        int u0  = (tid & 1) * 8;
        const __half* src = Q + (long)(b * SEQ + q0 + row) * DIM + h * HD;
#pragma unroll
        for (int p = 0; p < 8; p++) {
            int u  = u0 + p;
            int uu = (u & 8) | ((u & 7) ^ (row & 7));
            cp_async16(su + ASQ + (uint32_t)(row * 256 + uu * 16), src + u * 8);
        }
        cp_commit();
    }

    const int lkrow = tid >> 2;
    const int lku   = tid & 3;
    auto load_kv = [&](int kt2, int bb2) {
        long roff = (long)(b * SEQ + kt2 * 64 + lkrow);
        const __half* ks = Kg + roff * KV_DIM + hk * HD;
        const __half* vs = Vg + roff * KV_DIM + hk * HD;
        uint32_t kd = su + (bb2 ? ASK1 : ASK0) + (uint32_t)(lkrow * 256);
        uint32_t vd = su + (bb2 ? ASV1 : ASV0) + (uint32_t)(lkrow * 256);
#pragma unroll
        for (int p = 0; p < 4; p++) {
            int u  = lku + p * 4;
            int uu = (u & 8) | ((u & 7) ^ (lkrow & 7));
            cp_async16(kd + (uint32_t)(uu * 16), ks + u * 8);
            cp_async16(vd + (uint32_t)(uu * 16), vs + u * 8);
        }
    };

    load_kv(0, 0);
    cp_commit();
    load_kv(1, 1);
    cp_commit();

    float oacc[16][4];
    for (int nt = 0; nt < 16; nt++) {
        for (int r = 0; r < 4; r++) {
            oacc[nt][r] = 0.f;
        }
    }
    float m0 = -1e30f, m1 = -1e30f, l0 = 0.f, l1 = 0.f;

    for (int kt = 0; kt < 32; kt++) {
        cp_wait<1>();
        __syncthreads();

        int bb = kt & 1;
        const uint32_t Kbase = su + (bb ? ASK1 : ASK0);
        const uint32_t Vbase = su + (bb ? ASV1 : ASV0);

        float sc[8][4];
        for (int nt = 0; nt < 8; nt++) {
            for (int r = 0; r < 4; r++) {
                sc[nt][r] = 0.f;
            }
        }
#pragma unroll
        for (int kk = 0; kk < 8; kk++) {
            int u = 2 * kk + gsel;
            uint32_t af[4];
            {
                int uu = (u & 8) | ((u & 7) ^ (qrow & 7));
                ldsm4(af[0], af[1], af[2], af[3],
                      su + ASQ + (uint32_t)(qrow * 256 + uu * 16));
            }
            uint32_t bf[4][4];
#pragma unroll
            for (int jp = 0; jp < 4; jp++) {
                int row = jp * 16 + frow;
                int uu  = (u & 8) | ((u & 7) ^ (row & 7));
                ldsm4(bf[jp][0], bf[jp][1], bf[jp][2], bf[jp][3],
                      Kbase + (uint32_t)(row * 256 + uu * 16));
            }
#pragma unroll
            for (int nt = 0; nt < 8; nt++) {
                mma_f16(sc[nt], af, bf[nt >> 1][nt & 1], bf[nt >> 1][(nt & 1) + 2]);
            }
        }

        {
            float mx0 = -1e30f, mx1 = -1e30f;
#pragma unroll
            for (int nt = 0; nt < 8; nt++) {
                mx0 = fmaxf(mx0, fmaxf(sc[nt][0], sc[nt][1]));
                mx1 = fmaxf(mx1, fmaxf(sc[nt][2], sc[nt][3]));
            }
            mx0 = fmaxf(mx0, __shfl_xor_sync(0xffffffffu, mx0, 1));
            mx0 = fmaxf(mx0, __shfl_xor_sync(0xffffffffu, mx0, 2));
            mx1 = fmaxf(mx1, __shfl_xor_sync(0xffffffffu, mx1, 1));
            mx1 = fmaxf(mx1, __shfl_xor_sync(0xffffffffu, mx1, 2));
            float nm0 = fmaxf(m0, mx0);
            float nm1 = fmaxf(m1, mx1);
            float cf0 = __expf(m0 - nm0);
            float cf1 = __expf(m1 - nm1);
            m0 = nm0;
            m1 = nm1;

            const int g  = lane >> 2;
            const int t2 = (lane & 3) * 2;
            const int prow0 = warp * 16 + g;
            const int prow1 = prow0 + 8;
            float ps0 = 0.f, ps1 = 0.f;
#pragma unroll
            for (int nt = 0; nt < 8; nt++) {
                float p0 = __expf(sc[nt][0] - nm0);
                float p1 = __expf(sc[nt][1] - nm0);
                float p2 = __expf(sc[nt][2] - nm1);
                float p3 = __expf(sc[nt][3] - nm1);
                ps0 += p0 + p1;
                ps1 += p2 + p3;
                __half2 h01 = __floats2half2_rn(p0, p1);
                __half2 h23 = __floats2half2_rn(p2, p3);
                int uu0 = nt ^ (prow0 & 7);
                int uu1 = nt ^ (prow1 & 7);
                *(__half2*)(smc + ASPS + prow0 * 128 + uu0 * 16 + t2 * 2) = h01;
                *(__half2*)(smc + ASPS + prow1 * 128 + uu1 * 16 + t2 * 2) = h23;
            }
            ps0 += __shfl_xor_sync(0xffffffffu, ps0, 1);
            ps0 += __shfl_xor_sync(0xffffffffu, ps0, 2);
            ps1 += __shfl_xor_sync(0xffffffffu, ps1, 1);
            ps1 += __shfl_xor_sync(0xffffffffu, ps1, 2);
            l0 = l0 * cf0 + ps0;
            l1 = l1 * cf1 + ps1;
#pragma unroll
            for (int nt = 0; nt < 16; nt++) {
                oacc[nt][0] *= cf0;
                oacc[nt][1] *= cf0;
                oacc[nt][2] *= cf1;
                oacc[nt][3] *= cf1;
            }
        }
        __syncwarp();

#pragma unroll
        for (int k2 = 0; k2 < 4; k2++) {
            uint32_t af[4];
            {
                int u  = 2 * k2 + gsel;
                int uu = u ^ (qrow & 7);
                ldsm4(af[0], af[1], af[2], af[3],
                      su + ASPS + (uint32_t)(qrow * 128 + uu * 16));
            }
            uint32_t vf[8][4];
#pragma unroll
            for (int jp = 0; jp < 8; jp++) {
                int row = k2 * 16 + frow;
                int u   = 2 * jp + gsel;
                int uu  = (u & 8) | ((u & 7) ^ (row & 7));
                ldsm4t(vf[jp][0], vf[jp][1], vf[jp][2], vf[jp][3],
                       Vbase + (uint32_t)(row * 256 + uu * 16));
            }
#pragma unroll
            for (int jp = 0; jp < 8; jp++) {
                mma_f16(oacc[jp * 2],     af, vf[jp][0], vf[jp][1]);
                mma_f16(oacc[jp * 2 + 1], af, vf[jp][2], vf[jp][3]);
            }
        }
        __syncthreads();

        if (kt + 2 < 32) {
            load_kv(kt + 2, bb);
        }
        cp_commit();
    }

    {
        float r0 = 1.f / l0;
        float r1 = 1.f / l1;
        const int g  = lane >> 2;
        const int t2 = (lane & 3) * 2;
        int row0 = q0 + warp * 16 + g;
        __half* op0 = O + (long)(b * SEQ + row0) * DIM + h * HD;
        __half* op1 = op0 + (long)8 * DIM;
#pragma unroll
        for (int nt = 0; nt < 16; nt++) {
            *(__half2*)(op0 + nt * 8 + t2) =
                __floats2half2_rn(oacc[nt][0] * r0, oacc[nt][1] * r0);
            *(__half2*)(op1 + nt * 8 + t2) =
                __floats2half2_rn(oacc[nt][2] * r1, oacc[nt][3] * r1);
        }
    }
}

// ==================================================================
// Launch
// ==================================================================
extern "C" void kernel_launch(void* const* d_in, const int* in_sizes, int n_in,
                              void* d_out, int out_size)
{
    (void)in_sizes;
    (void)n_in;
    (void)out_size;
    const float* x  = (const float*)d_in[0];
    const float* wq = (const float*)d_in[1];
    const float* wk = (const float*)d_in[2];
    const float* wv = (const float*)d_in[3];
    const float* wo = (const float*)d_in[4];
    const int*   sp = (const int*)d_in[5];
    float* out = (float*)d_out;

    float* q;
    float* k;
    float* v;
    __half* hx;
    __half* hwq;
    __half* hwk;
    __half* hwv;
    __half* hwo;
    __half* hq;
    __half* hkb;
    __half* hvb;
    __half* ho;
    cudaGetSymbolAddress((void**)&q,    g_q);
    cudaGetSymbolAddress((void**)&k,    g_k);
    cudaGetSymbolAddress((void**)&v,    g_v);
    cudaGetSymbolAddress((void**)&hx,   g_hx);
    cudaGetSymbolAddress((void**)&hwq,  g_hwq);
    cudaGetSymbolAddress((void**)&hwk,  g_hwk);
    cudaGetSymbolAddress((void**)&hwv,  g_hwv);
    cudaGetSymbolAddress((void**)&hwo,  g_hwo);
    cudaGetSymbolAddress((void**)&hq,   g_hq);
    cudaGetSymbolAddress((void**)&hkb,  g_hk);
    cudaGetSymbolAddress((void**)&hvb,  g_hv);
    cudaGetSymbolAddress((void**)&ho,   g_ho);

    cudaFuncSetAttribute(gemm_qkv,
                         cudaFuncAttributeMaxDynamicSharedMemorySize, HGEMM_SMEM);
    cudaFuncSetAttribute(gemm_wo,
                         cudaFuncAttributeMaxDynamicSharedMemorySize, HGEMM_SMEM);
    cudaFuncSetAttribute(attn_f16_kernel,
                         cudaFuncAttributeMaxDynamicSharedMemorySize, ATTN_SMEM);

    // all 5 input conversions in one launch
    {
        int n4x  = MROWS * DIM / 4;    // 4M
        int n4q  = DIM * DIM / 4;      // 4M
        int n4kv = KV_DIM * DIM / 4;   // 1M
        int total = n4x + n4q + 2 * n4kv + n4q;
        to_half5_kernel<<<(total + 255) / 256, 256>>>(
            x, hx, n4x, wq, hwq, n4q, wk, hwk, n4kv, wv, hwv, n4kv, wo, hwo, n4q);
    }

    // fused Q+K+V projections (1536 CTAs)
    gemm_qkv<<<1536, 256, HGEMM_SMEM>>>(hx, hwq, hwk, hwv, q, k, v);

    rope_half_kernel<<<(MROWS * NHQ * 64) / 256, 256>>>(q, hq, sp, NHQ, DIM,
                                                        0.08838834764831845f);
    rope_half_kernel<<<(MROWS * NHK * 64) / 256, 256>>>(k, hkb, sp, NHK, KV_DIM, 1.0f);
    {
        int n4v = MROWS * KV_DIM / 4;
        to_half_kernel<<<(n4v + 255) / 256, 256>>>(v, hvb, n4v);
    }

    dim3 ga(SEQ / 128, NHQ, BATCH);
    attn_f16_kernel<<<ga, 256, ATTN_SMEM>>>(hq, hkb, hvb, ho);

    dim3 gw(DIM / HBN, MROWS / HBM);
    gemm_wo<<<gw, 256, HGEMM_SMEM>>>(ho, hwo, out, DIM, DIM);
}

// round 15
// speedup vs baseline: 2.2205x; 1.8647x over previous
#include <cuda_runtime.h>
#include <cuda_fp16.h>
#include <cstdint>
#include <math.h>

#define BATCH 2
#define SEQ   2048
#define DIM   4096
#define KV_DIM 1024
#define NHQ   32
#define NHK   8
#define HD    128
#define MROWS (BATCH*SEQ)

// scratch (no allocations allowed)
__device__ float g_q[MROWS*DIM];
__device__ float g_k[MROWS*KV_DIM];
__device__ float g_v[MROWS*KV_DIM];
__device__ __half g_hx[MROWS*DIM];
__device__ __half g_hwq[DIM*DIM];
__device__ __half g_hwk[KV_DIM*DIM];
__device__ __half g_hwv[KV_DIM*DIM];
__device__ __half g_hwo[DIM*DIM];
__device__ __half g_hq[MROWS*DIM];
__device__ __half g_hk[MROWS*KV_DIM];
__device__ __half g_hv[MROWS*KV_DIM];
__device__ __half g_ho[MROWS*DIM];
__device__ float g_invf[64];

// ==================================================================
// helpers
// ==================================================================
__device__ __forceinline__ void ldsm4(uint32_t& r0, uint32_t& r1,
                                      uint32_t& r2, uint32_t& r3, uint32_t addr)
{
    asm volatile("ldmatrix.sync.aligned.m8n8.x4.shared.b16 {%0,%1,%2,%3}, [%4];"
                 : "=r"(r0), "=r"(r1), "=r"(r2), "=r"(r3) : "r"(addr));
}

__device__ __forceinline__ void ldsm4t(uint32_t& r0, uint32_t& r1,
                                       uint32_t& r2, uint32_t& r3, uint32_t addr)
{
    asm volatile("ldmatrix.sync.aligned.m8n8.x4.trans.shared.b16 {%0,%1,%2,%3}, [%4];"
                 : "=r"(r0), "=r"(r1), "=r"(r2), "=r"(r3) : "r"(addr));
}

__device__ __forceinline__ void mma_f16(float* d, const uint32_t* a,
                                        uint32_t b0, uint32_t b1)
{
    asm volatile("mma.sync.aligned.m16n8k16.row.col.f32.f16.f16.f32 "
                 "{%0,%1,%2,%3},{%4,%5,%6,%7},{%8,%9},{%0,%1,%2,%3};"
                 : "+f"(d[0]), "+f"(d[1]), "+f"(d[2]), "+f"(d[3])
                 : "r"(a[0]), "r"(a[1]), "r"(a[2]), "r"(a[3]),
                   "r"(b0), "r"(b1));
}

__device__ __forceinline__ void cp_async16(uint32_t dst, const void* src)
{
    asm volatile("cp.async.cg.shared.global [%0], [%1], 16;" :: "r"(dst), "l"(src));
}
__device__ __forceinline__ void cp_commit()
{
    asm volatile("cp.async.commit_group;");
}
template<int N> __device__ __forceinline__ void cp_wait()
{
    asm volatile("cp.async.wait_group %0;" :: "n"(N));
}

// ==================================================================
// conversion kernels
// ==================================================================
__global__ void to_half_kernel(const float* __restrict__ in,
                               __half* __restrict__ out, int n4)
{
    int i = blockIdx.x * blockDim.x + threadIdx.x;
    if (i < n4) {
        float4 v = ((const float4*)in)[i];
        ((__half2*)out)[i * 2]     = __floats2half2_rn(v.x, v.y);
        ((__half2*)out)[i * 2 + 1] = __floats2half2_rn(v.z, v.w);
    }
}

__global__ void to_half5_kernel(const float* s0, __half* d0, int n0,
                                const float* s1, __half* d1, int n1,
                                const float* s2, __half* d2, int n2,
                                const float* s3, __half* d3, int n3,
                                const float* s4, __half* d4, int n4)
{
    int j = blockIdx.x * blockDim.x + threadIdx.x;
    const float* in;
    __half* out;
    if (j < n0) { in = s0; out = d0; }
    else {
        j -= n0;
        if (j < n1) { in = s1; out = d1; }
        else {
            j -= n1;
            if (j < n2) { in = s2; out = d2; }
            else {
                j -= n2;
                if (j < n3) { in = s3; out = d3; }
                else {
                    j -= n3;
                    if (j >= n4) { return; }
                    in = s4; out = d4;
                }
            }
        }
    }
    float4 v = ((const float4*)in)[j];
    ((__half2*)out)[j * 2]     = __floats2half2_rn(v.x, v.y);
    ((__half2*)out)[j * 2 + 1] = __floats2half2_rn(v.z, v.w);
}

// ==================================================================
// inv_freq table: 64 values, bit-identical to previous per-thread calc
// ==================================================================
__global__ void invf_kernel(float* __restrict__ tbl)
{
    int i = threadIdx.x;
    if (i < 64) {
        tbl[i] = (float)pow(10000.0, -(double)i / 64.0);
    }
}

// ==================================================================
// FP16 GEMM body (proven core)
// ==================================================================
#define HBM 128
#define HBN 128
#define HBK 64
#define HSTAGES 3
#define HSTAGE_BYTES 32768
#define HGEMM_SMEM (HSTAGES*HSTAGE_BYTES)

__device__ __forceinline__ void gemm_body(const __half* __restrict__ A,
                                          const __half* __restrict__ B,
                                          float* __restrict__ C,
                                          int N, int K, int bm, int bn,
                                          char* hsm)
{
    const uint32_t su = (uint32_t)__cvta_generic_to_shared(hsm);

    const int tid  = threadIdx.x;
    const int lane = tid & 31;
    const int warp = tid >> 5;
    const int wm   = warp & 3;
    const int wn   = warp >> 2;

    const int lrow = tid >> 1;
    const int lu0  = (tid & 1) * 4;
    const __half* Ap = A + (long)(bm * HBM + lrow) * K;
    const __half* Bp = B + (long)(bn * HBN + lrow) * K;
    const uint32_t aDst = su + (uint32_t)(lrow * 128);
    const uint32_t bDst = aDst + 16384u;
    const int lsw = lrow & 7;

    const int grp = lane >> 3;
    const int lr  = lane & 7;
    const int frow = lr + 8 * (grp & 1);
    const int gk   = grp >> 1;
    const int rowA = wm * 32 + frow;
    const int rowB = wn * 64 + frow;
    const int swA = rowA & 7;
    const int swB = rowB & 7;
    const uint32_t aRowOff = (uint32_t)rowA * 128u;
    const uint32_t bRowOff = (uint32_t)rowB * 128u;

    float c[2][8][4];
    for (int mt = 0; mt < 2; mt++) {
        for (int nt = 0; nt < 8; nt++) {
            for (int r = 0; r < 4; r++) {
                c[mt][nt][r] = 0.f;
            }
        }
    }

    const int T = K / HBK;

    for (int s = 0; s < HSTAGES - 1; s++) {
        int k0 = s * HBK;
        uint32_t ad = aDst + (uint32_t)s * HSTAGE_BYTES;
        uint32_t bd = bDst + (uint32_t)s * HSTAGE_BYTES;
#pragma unroll
        for (int p = 0; p < 4; p++) {
            int u = lu0 + p;
            uint32_t so = (uint32_t)((u ^ lsw) << 4);
            cp_async16(ad + so, Ap + k0 + u * 8);
            cp_async16(bd + so, Bp + k0 + u * 8);
        }
        cp_commit();
    }

    for (int ks = 0; ks < T; ks++) {
        cp_wait<HSTAGES - 2>();
        __syncthreads();

        int nk = ks + HSTAGES - 1;
        if (nk < T) {
            int slot = nk % HSTAGES;
            int k0 = nk * HBK;
            uint32_t ad = aDst + (uint32_t)slot * HSTAGE_BYTES;
            uint32_t bd = bDst + (uint32_t)slot * HSTAGE_BYTES;
#pragma unroll
            for (int p = 0; p < 4; p++) {
                int u = lu0 + p;
                uint32_t so = (uint32_t)((u ^ lsw) << 4);
                cp_async16(ad + so, Ap + k0 + u * 8);
                cp_async16(bd + so, Bp + k0 + u * 8);
            }
            cp_commit();
        }

        const uint32_t Abase = su + (uint32_t)((ks % HSTAGES) * HSTAGE_BYTES);
        const uint32_t Bbase = Abase + 16384u;

#pragma unroll
        for (int kk = 0; kk < 4; kk++) {
            int u = kk * 2 + gk;
            uint32_t af0[4];
            uint32_t af1[4];
            uint32_t aAddr = Abase + aRowOff + (uint32_t)(((u ^ swA) & 7) << 4) +
                             (uint32_t)((u & 8) << 4);
            ldsm4(af0[0], af0[1], af0[2], af0[3], aAddr);
            ldsm4(af1[0], af1[1], af1[2], af1[3], aAddr + 2048u);

            uint32_t bf[4][4];
#pragma unroll
            for (int jp = 0; jp < 4; jp++) {
                uint32_t bAddr = Bbase + bRowOff + (uint32_t)(jp * 2048) +
                                 (uint32_t)(((u ^ swB) & 7) << 4) +
                                 (uint32_t)((u & 8) << 4);
                ldsm4(bf[jp][0], bf[jp][1], bf[jp][2], bf[jp][3], bAddr);
            }

#pragma unroll
            for (int nt = 0; nt < 8; nt++) {
                uint32_t b0 = bf[nt >> 1][nt & 1];
                uint32_t b1 = bf[nt >> 1][(nt & 1) + 2];
                mma_f16(c[0][nt], af0, b0, b1);
                mma_f16(c[1][nt], af1, b0, b1);
            }
        }
    }

    const int g  = lane >> 2;
    const int t2 = (lane & 3) * 2;
    for (int mt = 0; mt < 2; mt++) {
        int row0 = bm * HBM + wm * 32 + mt * 16 + g;
        for (int nt = 0; nt < 8; nt++) {
            int col = bn * HBN + wn * 64 + nt * 8 + t2;
            *(float2*)(C + (long)row0 * N + col)       = make_float2(c[mt][nt][0], c[mt][nt][1]);
            *(float2*)(C + (long)(row0 + 8) * N + col) = make_float2(c[mt][nt][2], c[mt][nt][3]);
        }
    }
}

__global__ __launch_bounds__(256, 2)
void gemm_qkv(const __half* __restrict__ hx,
              const __half* __restrict__ hwq,
              const __half* __restrict__ hwk,
              const __half* __restrict__ hwv,
              float* __restrict__ q, float* __restrict__ k, float* __restrict__ v)
{
    extern __shared__ char hsm[];
    int idx = blockIdx.x;
    const __half* B;
    float* C;
    int N;
    int bm;
    int bn;
    if (idx < 1024) {
        B = hwq; C = q; N = DIM;
        bn = idx & 31; bm = idx >> 5;
    } else {
        int t = idx - 1024;
        if (t < 256) { B = hwk; C = k; }
        else { B = hwv; C = v; t -= 256; }
        N = KV_DIM;
        bn = t & 7; bm = t >> 3;
    }
    gemm_body(hx, B, C, N, DIM, bm, bn, hsm);
}

__global__ __launch_bounds__(256, 2)
void gemm_wo(const __half* __restrict__ A, const __half* __restrict__ B,
             float* __restrict__ C, int N, int K)
{
    extern __shared__ char hsm[];
    gemm_body(A, B, C, N, K, blockIdx.y, blockIdx.x, hsm);
}

// ==================================================================
// RoPE: one thread per (row, i); sincos computed once, reused over
// all Q heads and all K heads. Per-element math bit-identical to R14.
// ==================================================================
__global__ void rope_both_kernel(const float* __restrict__ qsrc,
                                 __half* __restrict__ qdst,
                                 const float* __restrict__ ksrc,
                                 __half* __restrict__ kdst,
                                 const int* __restrict__ sp,
                                 const float* __restrict__ invf_tbl,
                                 float qscale)
{
    int idx = blockIdx.x * blockDim.x + threadIdx.x;   // over MROWS*64
    int i   = idx & 63;
    int row = idx >> 6;
    int pos = (row % SEQ) + sp[0];

    float invf = invf_tbl[i];
    float ang  = __fmul_rn((float)pos, invf);
    float sn;
    float cs;
    sincosf(ang, &sn, &cs);

    const float2* qs = (const float2*)(qsrc + (long)row * DIM) + i;
    __half2*      qd = (__half2*)(qdst + (long)row * DIM) + i;
#pragma unroll
    for (int h = 0; h < NHQ; h++) {
        float2 v = qs[h * (HD / 2)];
        float o0 = (v.x * cs - v.y * sn) * qscale;
        float o1 = (v.x * sn + v.y * cs) * qscale;
        qd[h * (HD / 2)] = __floats2half2_rn(o0, o1);
    }

    const float2* ks = (const float2*)(ksrc + (long)row * KV_DIM) + i;
    __half2*      kd = (__half2*)(kdst + (long)row * KV_DIM) + i;
#pragma unroll
    for (int h = 0; h < NHK; h++) {
        float2 v = ks[h * (HD / 2)];
        float o0 = v.x * cs - v.y * sn;
        float o1 = v.x * sn + v.y * cs;
        kd[h * (HD / 2)] = __floats2half2_rn(o0, o1);
    }
}

// ==================================================================
// FP16 flash attention (R14, proven)
// ==================================================================
#define ASQ  0
#define ASK0 32768
#define ASK1 49152
#define ASV0 65536
#define ASV1 81920
#define ASPS 98304
#define ATTN_SMEM 114688

__global__ __launch_bounds__(256, 2)
void attn_f16_kernel(const __half* __restrict__ Q, const __half* __restrict__ Kg,
                     const __half* __restrict__ Vg, __half* __restrict__ O)
{
    extern __shared__ char smc[];
    const uint32_t su = (uint32_t)__cvta_generic_to_shared(smc);
    const int tid  = threadIdx.x;
    const int lane = tid & 31;
    const int warp = tid >> 5;
    const int qt = blockIdx.x;
    const int h  = blockIdx.y;
    const int b  = blockIdx.z;
    const int hk = h >> 2;
    const int q0 = qt * 128;

    const int grp  = lane >> 3;
    const int lr   = lane & 7;
    const int frow = lr + 8 * (grp & 1);
    const int gsel = grp >> 1;
    const int qrow = warp * 16 + frow;

    {
        int row = tid >> 1;
        int u0  = (tid & 1) * 8;
        const __half* src = Q + (long)(b * SEQ + q0 + row) * DIM + h * HD;
#pragma unroll
        for (int p = 0; p < 8; p++) {
            int u  = u0 + p;
            int uu = (u & 8) | ((u & 7) ^ (row & 7));
            cp_async16(su + ASQ + (uint32_t)(row * 256 + uu * 16), src + u * 8);
        }
        cp_commit();
    }

    const int lkrow = tid >> 2;
    const int lku   = tid & 3;
    auto load_kv = [&](int kt2, int bb2) {
        long roff = (long)(b * SEQ + kt2 * 64 + lkrow);
        const __half* ks = Kg + roff * KV_DIM + hk * HD;
        const __half* vs = Vg + roff * KV_DIM + hk * HD;
        uint32_t kd = su + (bb2 ? ASK1 : ASK0) + (uint32_t)(lkrow * 256);
        uint32_t vd = su + (bb2 ? ASV1 : ASV0) + (uint32_t)(lkrow * 256);
#pragma unroll
        for (int p = 0; p < 4; p++) {
            int u  = lku + p * 4;
            int uu = (u & 8) | ((u & 7) ^ (lkrow & 7));
            cp_async16(kd + (uint32_t)(uu * 16), ks + u * 8);
            cp_async16(vd + (uint32_t)(uu * 16), vs + u * 8);
        }
    };

    load_kv(0, 0);
    cp_commit();
    load_kv(1, 1);
    cp_commit();

    float oacc[16][4];
    for (int nt = 0; nt < 16; nt++) {
        for (int r = 0; r < 4; r++) {
            oacc[nt][r] = 0.f;
        }
    }
    float m0 = -1e30f, m1 = -1e30f, l0 = 0.f, l1 = 0.f;

    for (int kt = 0; kt < 32; kt++) {
        cp_wait<1>();
        __syncthreads();

        int bb = kt & 1;
        const uint32_t Kbase = su + (bb ? ASK1 : ASK0);
        const uint32_t Vbase = su + (bb ? ASV1 : ASV0);

        float sc[8][4];
        for (int nt = 0; nt < 8; nt++) {
            for (int r = 0; r < 4; r++) {
                sc[nt][r] = 0.f;
            }
        }
#pragma unroll
        for (int kk = 0; kk < 8; kk++) {
            int u = 2 * kk + gsel;
            uint32_t af[4];
            {
                int uu = (u & 8) | ((u & 7) ^ (qrow & 7));
                ldsm4(af[0], af[1], af[2], af[3],
                      su + ASQ + (uint32_t)(qrow * 256 + uu * 16));
            }
            uint32_t bf[4][4];
#pragma unroll
            for (int jp = 0; jp < 4; jp++) {
                int row = jp * 16 + frow;
                int uu  = (u & 8) | ((u & 7) ^ (row & 7));
                ldsm4(bf[jp][0], bf[jp][1], bf[jp][2], bf[jp][3],
                      Kbase + (uint32_t)(row * 256 + uu * 16));
            }
#pragma unroll
            for (int nt = 0; nt < 8; nt++) {
                mma_f16(sc[nt], af, bf[nt >> 1][nt & 1], bf[nt >> 1][(nt & 1) + 2]);
            }
        }

        {
            float mx0 = -1e30f, mx1 = -1e30f;
#pragma unroll
            for (int nt = 0; nt < 8; nt++) {
                mx0 = fmaxf(mx0, fmaxf(sc[nt][0], sc[nt][1]));
                mx1 = fmaxf(mx1, fmaxf(sc[nt][2], sc[nt][3]));
            }
            mx0 = fmaxf(mx0, __shfl_xor_sync(0xffffffffu, mx0, 1));
            mx0 = fmaxf(mx0, __shfl_xor_sync(0xffffffffu, mx0, 2));
            mx1 = fmaxf(mx1, __shfl_xor_sync(0xffffffffu, mx1, 1));
            mx1 = fmaxf(mx1, __shfl_xor_sync(0xffffffffu, mx1, 2));
            float nm0 = fmaxf(m0, mx0);
            float nm1 = fmaxf(m1, mx1);
            float cf0 = __expf(m0 - nm0);
            float cf1 = __expf(m1 - nm1);
            m0 = nm0;
            m1 = nm1;

            const int g  = lane >> 2;
            const int t2 = (lane & 3) * 2;
            const int prow0 = warp * 16 + g;
            const int prow1 = prow0 + 8;
            float ps0 = 0.f, ps1 = 0.f;
#pragma unroll
            for (int nt = 0; nt < 8; nt++) {
                float p0 = __expf(sc[nt][0] - nm0);
                float p1 = __expf(sc[nt][1] - nm0);
                float p2 = __expf(sc[nt][2] - nm1);
                float p3 = __expf(sc[nt][3] - nm1);
                ps0 += p0 + p1;
                ps1 += p2 + p3;
                __half2 h01 = __floats2half2_rn(p0, p1);
                __half2 h23 = __floats2half2_rn(p2, p3);
                int uu0 = nt ^ (prow0 & 7);
                int uu1 = nt ^ (prow1 & 7);
                *(__half2*)(smc + ASPS + prow0 * 128 + uu0 * 16 + t2 * 2) = h01;
                *(__half2*)(smc + ASPS + prow1 * 128 + uu1 * 16 + t2 * 2) = h23;
            }
            ps0 += __shfl_xor_sync(0xffffffffu, ps0, 1);
            ps0 += __shfl_xor_sync(0xffffffffu, ps0, 2);
            ps1 += __shfl_xor_sync(0xffffffffu, ps1, 1);
            ps1 += __shfl_xor_sync(0xffffffffu, ps1, 2);
            l0 = l0 * cf0 + ps0;
            l1 = l1 * cf1 + ps1;
#pragma unroll
            for (int nt = 0; nt < 16; nt++) {
                oacc[nt][0] *= cf0;
                oacc[nt][1] *= cf0;
                oacc[nt][2] *= cf1;
                oacc[nt][3] *= cf1;
            }
        }
        __syncwarp();

#pragma unroll
        for (int k2 = 0; k2 < 4; k2++) {
            uint32_t af[4];
            {
                int u  = 2 * k2 + gsel;
                int uu = u ^ (qrow & 7);
                ldsm4(af[0], af[1], af[2], af[3],
                      su + ASPS + (uint32_t)(qrow * 128 + uu * 16));
            }
            uint32_t vf[8][4];
#pragma unroll
            for (int jp = 0; jp < 8; jp++) {
                int row = k2 * 16 + frow;
                int u   = 2 * jp + gsel;
                int uu  = (u & 8) | ((u & 7) ^ (row & 7));
                ldsm4t(vf[jp][0], vf[jp][1], vf[jp][2], vf[jp][3],
                       Vbase + (uint32_t)(row * 256 + uu * 16));
            }
#pragma unroll
            for (int jp = 0; jp < 8; jp++) {
                mma_f16(oacc[jp * 2],     af, vf[jp][0], vf[jp][1]);
                mma_f16(oacc[jp * 2 + 1], af, vf[jp][2], vf[jp][3]);
            }
        }
        __syncthreads();

        if (kt + 2 < 32) {
            load_kv(kt + 2, bb);
        }
        cp_commit();
    }

    {
        float r0 = 1.f / l0;
        float r1 = 1.f / l1;
        const int g  = lane >> 2;
        const int t2 = (lane & 3) * 2;
        int row0 = q0 + warp * 16 + g;
        __half* op0 = O + (long)(b * SEQ + row0) * DIM + h * HD;
        __half* op1 = op0 + (long)8 * DIM;
#pragma unroll
        for (int nt = 0; nt < 16; nt++) {
            *(__half2*)(op0 + nt * 8 + t2) =
                __floats2half2_rn(oacc[nt][0] * r0, oacc[nt][1] * r0);
            *(__half2*)(op1 + nt * 8 + t2) =
                __floats2half2_rn(oacc[nt][2] * r1, oacc[nt][3] * r1);
        }
    }
}

// ==================================================================
// Launch
// ==================================================================
extern "C" void kernel_launch(void* const* d_in, const int* in_sizes, int n_in,
                              void* d_out, int out_size)
{
    (void)in_sizes;
    (void)n_in;
    (void)out_size;
    const float* x  = (const float*)d_in[0];
    const float* wq = (const float*)d_in[1];
    const float* wk = (const float*)d_in[2];
    const float* wv = (const float*)d_in[3];
    const float* wo = (const float*)d_in[4];
    const int*   sp = (const int*)d_in[5];
    float* out = (float*)d_out;

    float* q;
    float* k;
    float* v;
    __half* hx;
    __half* hwq;
    __half* hwk;
    __half* hwv;
    __half* hwo;
    __half* hq;
    __half* hkb;
    __half* hvb;
    __half* ho;
    float* invf;
    cudaGetSymbolAddress((void**)&q,    g_q);
    cudaGetSymbolAddress((void**)&k,    g_k);
    cudaGetSymbolAddress((void**)&v,    g_v);
    cudaGetSymbolAddress((void**)&hx,   g_hx);
    cudaGetSymbolAddress((void**)&hwq,  g_hwq);
    cudaGetSymbolAddress((void**)&hwk,  g_hwk);
    cudaGetSymbolAddress((void**)&hwv,  g_hwv);
    cudaGetSymbolAddress((void**)&hwo,  g_hwo);
    cudaGetSymbolAddress((void**)&hq,   g_hq);
    cudaGetSymbolAddress((void**)&hkb,  g_hk);
    cudaGetSymbolAddress((void**)&hvb,  g_hv);
    cudaGetSymbolAddress((void**)&ho,   g_ho);
    cudaGetSymbolAddress((void**)&invf, g_invf);

    cudaFuncSetAttribute(gemm_qkv,
                         cudaFuncAttributeMaxDynamicSharedMemorySize, HGEMM_SMEM);
    cudaFuncSetAttribute(gemm_wo,
                         cudaFuncAttributeMaxDynamicSharedMemorySize, HGEMM_SMEM);
    cudaFuncSetAttribute(attn_f16_kernel,
                         cudaFuncAttributeMaxDynamicSharedMemorySize, ATTN_SMEM);

    invf_kernel<<<1, 64>>>(invf);

    {
        int n4x  = MROWS * DIM / 4;
        int n4q  = DIM * DIM / 4;
        int n4kv = KV_DIM * DIM / 4;
        int total = n4x + n4q + 2 * n4kv + n4q;
        to_half5_kernel<<<(total + 255) / 256, 256>>>(
            x, hx, n4x, wq, hwq, n4q, wk, hwk, n4kv, wv, hwv, n4kv, wo, hwo, n4q);
    }

    gemm_qkv<<<1536, 256, HGEMM_SMEM>>>(hx, hwq, hwk, hwv, q, k, v);

    // rope (Q + K in one launch; sincos shared across heads)
    rope_both_kernel<<<(MROWS * 64) / 256, 256>>>(q, hq, k, hkb, sp, invf,
                                                  0.08838834764831845f);
    {
        int n4v = MROWS * KV_DIM / 4;
        to_half_kernel<<<(n4v + 255) / 256, 256>>>(v, hvb, n4v);
    }

    dim3 ga(SEQ / 128, NHQ, BATCH);
    attn_f16_kernel<<<ga, 256, ATTN_SMEM>>>(hq, hkb, hvb, ho);

    dim3 gw(DIM / HBN, MROWS / HBM);
    gemm_wo<<<gw, 256, HGEMM_SMEM>>>(ho, hwo, out, DIM, DIM);
}

// round 16
// speedup vs baseline: 2.2516x; 1.0140x over previous
#include <cuda_runtime.h>
#include <cuda_fp16.h>
#include <cstdint>
#include <math.h>

#define BATCH 2
#define SEQ   2048
#define DIM   4096
#define KV_DIM 1024
#define NHQ   32
#define NHK   8
#define HD    128
#define MROWS (BATCH*SEQ)

// scratch (no allocations allowed)
__device__ float g_q[MROWS*DIM];
__device__ float g_k[MROWS*KV_DIM];
__device__ __half g_hx[MROWS*DIM];
__device__ __half g_hwq[DIM*DIM];
__device__ __half g_hwk[KV_DIM*DIM];
__device__ __half g_hwv[KV_DIM*DIM];
__device__ __half g_hwo[DIM*DIM];
__device__ __half g_hq[MROWS*DIM];
__device__ __half g_hk[MROWS*KV_DIM];
__device__ __half g_hv[MROWS*KV_DIM];
__device__ __half g_ho[MROWS*DIM];
__device__ float g_invf[64];

// ==================================================================
// helpers
// ==================================================================
__device__ __forceinline__ void ldsm4(uint32_t& r0, uint32_t& r1,
                                      uint32_t& r2, uint32_t& r3, uint32_t addr)
{
    asm volatile("ldmatrix.sync.aligned.m8n8.x4.shared.b16 {%0,%1,%2,%3}, [%4];"
                 : "=r"(r0), "=r"(r1), "=r"(r2), "=r"(r3) : "r"(addr));
}

__device__ __forceinline__ void ldsm4t(uint32_t& r0, uint32_t& r1,
                                       uint32_t& r2, uint32_t& r3, uint32_t addr)
{
    asm volatile("ldmatrix.sync.aligned.m8n8.x4.trans.shared.b16 {%0,%1,%2,%3}, [%4];"
                 : "=r"(r0), "=r"(r1), "=r"(r2), "=r"(r3) : "r"(addr));
}

__device__ __forceinline__ void mma_f16(float* d, const uint32_t* a,
                                        uint32_t b0, uint32_t b1)
{
    asm volatile("mma.sync.aligned.m16n8k16.row.col.f32.f16.f16.f32 "
                 "{%0,%1,%2,%3},{%4,%5,%6,%7},{%8,%9},{%0,%1,%2,%3};"
                 : "+f"(d[0]), "+f"(d[1]), "+f"(d[2]), "+f"(d[3])
                 : "r"(a[0]), "r"(a[1]), "r"(a[2]), "r"(a[3]),
                   "r"(b0), "r"(b1));
}

__device__ __forceinline__ void cp_async16(uint32_t dst, const void* src)
{
    asm volatile("cp.async.cg.shared.global [%0], [%1], 16;" :: "r"(dst), "l"(src));
}
__device__ __forceinline__ void cp_commit()
{
    asm volatile("cp.async.commit_group;");
}
template<int N> __device__ __forceinline__ void cp_wait()
{
    asm volatile("cp.async.wait_group %0;" :: "n"(N));
}

// ==================================================================
// conversion kernels
// ==================================================================
__global__ void to_half5_kernel(const float* s0, __half* d0, int n0,
                                const float* s1, __half* d1, int n1,
                                const float* s2, __half* d2, int n2,
                                const float* s3, __half* d3, int n3,
                                const float* s4, __half* d4, int n4)
{
    int j = blockIdx.x * blockDim.x + threadIdx.x;
    const float* in;
    __half* out;
    if (j < n0) { in = s0; out = d0; }
    else {
        j -= n0;
        if (j < n1) { in = s1; out = d1; }
        else {
            j -= n1;
            if (j < n2) { in = s2; out = d2; }
            else {
                j -= n2;
                if (j < n3) { in = s3; out = d3; }
                else {
                    j -= n3;
                    if (j >= n4) { return; }
                    in = s4; out = d4;
                }
            }
        }
    }
    float4 v = ((const float4*)in)[j];
    ((__half2*)out)[j * 2]     = __floats2half2_rn(v.x, v.y);
    ((__half2*)out)[j * 2 + 1] = __floats2half2_rn(v.z, v.w);
}

// ==================================================================
// inv_freq table (bit-identical to per-thread calc)
// ==================================================================
__global__ void invf_kernel(float* __restrict__ tbl)
{
    int i = threadIdx.x;
    if (i < 64) {
        tbl[i] = (float)pow(10000.0, -(double)i / 64.0);
    }
}

// ==================================================================
// FP16 GEMM body — proven core + register-level fragment pipeline.
// Cf32 or Ch16 output (exactly one non-null).
// ==================================================================
#define HBM 128
#define HBN 128
#define HBK 64
#define HSTAGES 3
#define HSTAGE_BYTES 32768
#define HGEMM_SMEM (HSTAGES*HSTAGE_BYTES)

__device__ __forceinline__ void gemm_body(const __half* __restrict__ A,
                                          const __half* __restrict__ B,
                                          float* __restrict__ Cf32,
                                          __half* __restrict__ Ch16,
                                          int N, int K, int bm, int bn,
                                          char* hsm)
{
    const uint32_t su = (uint32_t)__cvta_generic_to_shared(hsm);

    const int tid  = threadIdx.x;
    const int lane = tid & 31;
    const int warp = tid >> 5;
    const int wm   = warp & 3;
    const int wn   = warp >> 2;

    const int lrow = tid >> 1;
    const int lu0  = (tid & 1) * 4;
    const __half* Ap = A + (long)(bm * HBM + lrow) * K;
    const __half* Bp = B + (long)(bn * HBN + lrow) * K;
    const uint32_t aDst = su + (uint32_t)(lrow * 128);
    const uint32_t bDst = aDst + 16384u;
    const int lsw = lrow & 7;

    const int grp = lane >> 3;
    const int lr  = lane & 7;
    const int frow = lr + 8 * (grp & 1);
    const int gk   = grp >> 1;
    const int rowA = wm * 32 + frow;
    const int rowB = wn * 64 + frow;
    const int swA = rowA & 7;
    const int swB = rowB & 7;
    const uint32_t aRowOff = (uint32_t)rowA * 128u;
    const uint32_t bRowOff = (uint32_t)rowB * 128u;

    float c[2][8][4];
    for (int mt = 0; mt < 2; mt++) {
        for (int nt = 0; nt < 8; nt++) {
            for (int r = 0; r < 4; r++) {
                c[mt][nt][r] = 0.f;
            }
        }
    }

    const int T = K / HBK;

    for (int s = 0; s < HSTAGES - 1; s++) {
        int k0 = s * HBK;
        uint32_t ad = aDst + (uint32_t)s * HSTAGE_BYTES;
        uint32_t bd = bDst + (uint32_t)s * HSTAGE_BYTES;
#pragma unroll
        for (int p = 0; p < 4; p++) {
            int u = lu0 + p;
            uint32_t so = (uint32_t)((u ^ lsw) << 4);
            cp_async16(ad + so, Ap + k0 + u * 8);
            cp_async16(bd + so, Bp + k0 + u * 8);
        }
        cp_commit();
    }

    // fragment double buffers
    uint32_t af0[2][4];
    uint32_t af1[2][4];
    uint32_t bf[2][4][4];

    auto load_frags = [&](uint32_t Abase, uint32_t Bbase, int kk, int buf) {
        int u = kk * 2 + gk;
        uint32_t aAddr = Abase + aRowOff + (uint32_t)(((u ^ swA) & 7) << 4) +
                         (uint32_t)((u & 8) << 4);
        ldsm4(af0[buf][0], af0[buf][1], af0[buf][2], af0[buf][3], aAddr);
        ldsm4(af1[buf][0], af1[buf][1], af1[buf][2], af1[buf][3], aAddr + 2048u);
#pragma unroll
        for (int jp = 0; jp < 4; jp++) {
            uint32_t bAddr = Bbase + bRowOff + (uint32_t)(jp * 2048) +
                             (uint32_t)(((u ^ swB) & 7) << 4) +
                             (uint32_t)((u & 8) << 4);
            ldsm4(bf[buf][jp][0], bf[buf][jp][1], bf[buf][jp][2], bf[buf][jp][3], bAddr);
        }
    };

    for (int ks = 0; ks < T; ks++) {
        cp_wait<HSTAGES - 2>();
        __syncthreads();

        int nk = ks + HSTAGES - 1;
        if (nk < T) {
            int slot = nk % HSTAGES;
            int k0 = nk * HBK;
            uint32_t ad = aDst + (uint32_t)slot * HSTAGE_BYTES;
            uint32_t bd = bDst + (uint32_t)slot * HSTAGE_BYTES;
#pragma unroll
            for (int p = 0; p < 4; p++) {
                int u = lu0 + p;
                uint32_t so = (uint32_t)((u ^ lsw) << 4);
                cp_async16(ad + so, Ap + k0 + u * 8);
                cp_async16(bd + so, Bp + k0 + u * 8);
            }
            cp_commit();
        }

        const uint32_t Abase = su + (uint32_t)((ks % HSTAGES) * HSTAGE_BYTES);
        const uint32_t Bbase = Abase + 16384u;

        load_frags(Abase, Bbase, 0, 0);
#pragma unroll
        for (int kk = 0; kk < 4; kk++) {
            int cur = kk & 1;
            if (kk < 3) {
                load_frags(Abase, Bbase, kk + 1, cur ^ 1);
            }
#pragma unroll
            for (int nt = 0; nt < 8; nt++) {
                uint32_t b0 = bf[cur][nt >> 1][nt & 1];
                uint32_t b1 = bf[cur][nt >> 1][(nt & 1) + 2];
                mma_f16(c[0][nt], af0[cur], b0, b1);
                mma_f16(c[1][nt], af1[cur], b0, b1);
            }
        }
    }

    const int g  = lane >> 2;
    const int t2 = (lane & 3) * 2;
    if (Cf32) {
        for (int mt = 0; mt < 2; mt++) {
            int row0 = bm * HBM + wm * 32 + mt * 16 + g;
            for (int nt = 0; nt < 8; nt++) {
                int col = bn * HBN + wn * 64 + nt * 8 + t2;
                *(float2*)(Cf32 + (long)row0 * N + col)       = make_float2(c[mt][nt][0], c[mt][nt][1]);
                *(float2*)(Cf32 + (long)(row0 + 8) * N + col) = make_float2(c[mt][nt][2], c[mt][nt][3]);
            }
        }
    } else {
        for (int mt = 0; mt < 2; mt++) {
            int row0 = bm * HBM + wm * 32 + mt * 16 + g;
            for (int nt = 0; nt < 8; nt++) {
                int col = bn * HBN + wn * 64 + nt * 8 + t2;
                *(__half2*)(Ch16 + (long)row0 * N + col) =
                    __floats2half2_rn(c[mt][nt][0], c[mt][nt][1]);
                *(__half2*)(Ch16 + (long)(row0 + 8) * N + col) =
                    __floats2half2_rn(c[mt][nt][2], c[mt][nt][3]);
            }
        }
    }
}

// fused Q+K+V projections (V written directly as fp16)
__global__ __launch_bounds__(256, 2)
void gemm_qkv(const __half* __restrict__ hx,
              const __half* __restrict__ hwq,
              const __half* __restrict__ hwk,
              const __half* __restrict__ hwv,
              float* __restrict__ q, float* __restrict__ k,
              __half* __restrict__ hv)
{
    extern __shared__ char hsm[];
    int idx = blockIdx.x;
    if (idx < 1024) {
        gemm_body(hx, hwq, q, nullptr, DIM, DIM, idx >> 5, idx & 31, hsm);
    } else {
        int t = idx - 1024;
        if (t < 256) {
            gemm_body(hx, hwk, k, nullptr, KV_DIM, DIM, t >> 3, t & 7, hsm);
        } else {
            t -= 256;
            gemm_body(hx, hwv, nullptr, hv, KV_DIM, DIM, t >> 3, t & 7, hsm);
        }
    }
}

__global__ __launch_bounds__(256, 2)
void gemm_wo(const __half* __restrict__ A, const __half* __restrict__ B,
             float* __restrict__ C, int N, int K)
{
    extern __shared__ char hsm[];
    gemm_body(A, B, C, nullptr, N, K, blockIdx.y, blockIdx.x, hsm);
}

// ==================================================================
// RoPE: one thread per (row, i); sincos shared across all heads
// ==================================================================
__global__ void rope_both_kernel(const float* __restrict__ qsrc,
                                 __half* __restrict__ qdst,
                                 const float* __restrict__ ksrc,
                                 __half* __restrict__ kdst,
                                 const int* __restrict__ sp,
                                 const float* __restrict__ invf_tbl,
                                 float qscale)
{
    int idx = blockIdx.x * blockDim.x + threadIdx.x;
    int i   = idx & 63;
    int row = idx >> 6;
    int pos = (row % SEQ) + sp[0];

    float invf = invf_tbl[i];
    float ang  = __fmul_rn((float)pos, invf);
    float sn;
    float cs;
    sincosf(ang, &sn, &cs);

    const float2* qs = (const float2*)(qsrc + (long)row * DIM) + i;
    __half2*      qd = (__half2*)(qdst + (long)row * DIM) + i;
#pragma unroll
    for (int h = 0; h < NHQ; h++) {
        float2 v = qs[h * (HD / 2)];
        float o0 = (v.x * cs - v.y * sn) * qscale;
        float o1 = (v.x * sn + v.y * cs) * qscale;
        qd[h * (HD / 2)] = __floats2half2_rn(o0, o1);
    }

    const float2* ks = (const float2*)(ksrc + (long)row * KV_DIM) + i;
    __half2*      kd = (__half2*)(kdst + (long)row * KV_DIM) + i;
#pragma unroll
    for (int h = 0; h < NHK; h++) {
        float2 v = ks[h * (HD / 2)];
        float o0 = v.x * cs - v.y * sn;
        float o1 = v.x * sn + v.y * cs;
        kd[h * (HD / 2)] = __floats2half2_rn(o0, o1);
    }
}

// ==================================================================
// FP16 flash attention (proven, unchanged)
// ==================================================================
#define ASQ  0
#define ASK0 32768
#define ASK1 49152
#define ASV0 65536
#define ASV1 81920
#define ASPS 98304
#define ATTN_SMEM 114688

__global__ __launch_bounds__(256, 2)
void attn_f16_kernel(const __half* __restrict__ Q, const __half* __restrict__ Kg,
                     const __half* __restrict__ Vg, __half* __restrict__ O)
{
    extern __shared__ char smc[];
    const uint32_t su = (uint32_t)__cvta_generic_to_shared(smc);
    const int tid  = threadIdx.x;
    const int lane = tid & 31;
    const int warp = tid >> 5;
    const int qt = blockIdx.x;
    const int h  = blockIdx.y;
    const int b  = blockIdx.z;
    const int hk = h >> 2;
    const int q0 = qt * 128;

    const int grp  = lane >> 3;
    const int lr   = lane & 7;
    const int frow = lr + 8 * (grp & 1);
    const int gsel = grp >> 1;
    const int qrow = warp * 16 + frow;

    {
        int row = tid >> 1;
        int u0  = (tid & 1) * 8;
        const __half* src = Q + (long)(b * SEQ + q0 + row) * DIM + h * HD;
#pragma unroll
        for (int p = 0; p < 8; p++) {
            int u  = u0 + p;
            int uu = (u & 8) | ((u & 7) ^ (row & 7));
            cp_async16(su + ASQ + (uint32_t)(row * 256 + uu * 16), src + u * 8);
        }
        cp_commit();
    }

    const int lkrow = tid >> 2;
    const int lku   = tid & 3;
    auto load_kv = [&](int kt2, int bb2) {
        long roff = (long)(b * SEQ + kt2 * 64 + lkrow);
        const __half* ks = Kg + roff * KV_DIM + hk * HD;
        const __half* vs = Vg + roff * KV_DIM + hk * HD;
        uint32_t kd = su + (bb2 ? ASK1 : ASK0) + (uint32_t)(lkrow * 256);
        uint32_t vd = su + (bb2 ? ASV1 : ASV0) + (uint32_t)(lkrow * 256);
#pragma unroll
        for (int p = 0; p < 4; p++) {
            int u  = lku + p * 4;
            int uu = (u & 8) | ((u & 7) ^ (lkrow & 7));
            cp_async16(kd + (uint32_t)(uu * 16), ks + u * 8);
            cp_async16(vd + (uint32_t)(uu * 16), vs + u * 8);
        }
    };

    load_kv(0, 0);
    cp_commit();
    load_kv(1, 1);
    cp_commit();

    float oacc[16][4];
    for (int nt = 0; nt < 16; nt++) {
        for (int r = 0; r < 4; r++) {
            oacc[nt][r] = 0.f;
        }
    }
    float m0 = -1e30f, m1 = -1e30f, l0 = 0.f, l1 = 0.f;

    for (int kt = 0; kt < 32; kt++) {
        cp_wait<1>();
        __syncthreads();

        int bb = kt & 1;
        const uint32_t Kbase = su + (bb ? ASK1 : ASK0);
        const uint32_t Vbase = su + (bb ? ASV1 : ASV0);

        float sc[8][4];
        for (int nt = 0; nt < 8; nt++) {
            for (int r = 0; r < 4; r++) {
                sc[nt][r] = 0.f;
            }
        }
#pragma unroll
        for (int kk = 0; kk < 8; kk++) {
            int u = 2 * kk + gsel;
            uint32_t af[4];
            {
                int uu = (u & 8) | ((u & 7) ^ (qrow & 7));
                ldsm4(af[0], af[1], af[2], af[3],
                      su + ASQ + (uint32_t)(qrow * 256 + uu * 16));
            }
            uint32_t bf[4][4];
#pragma unroll
            for (int jp = 0; jp < 4; jp++) {
                int row = jp * 16 + frow;
                int uu  = (u & 8) | ((u & 7) ^ (row & 7));
                ldsm4(bf[jp][0], bf[jp][1], bf[jp][2], bf[jp][3],
                      Kbase + (uint32_t)(row * 256 + uu * 16));
            }
#pragma unroll
            for (int nt = 0; nt < 8; nt++) {
                mma_f16(sc[nt], af, bf[nt >> 1][nt & 1], bf[nt >> 1][(nt & 1) + 2]);
            }
        }

        {
            float mx0 = -1e30f, mx1 = -1e30f;
#pragma unroll
            for (int nt = 0; nt < 8; nt++) {
                mx0 = fmaxf(mx0, fmaxf(sc[nt][0], sc[nt][1]));
                mx1 = fmaxf(mx1, fmaxf(sc[nt][2], sc[nt][3]));
            }
            mx0 = fmaxf(mx0, __shfl_xor_sync(0xffffffffu, mx0, 1));
            mx0 = fmaxf(mx0, __shfl_xor_sync(0xffffffffu, mx0, 2));
            mx1 = fmaxf(mx1, __shfl_xor_sync(0xffffffffu, mx1, 1));
            mx1 = fmaxf(mx1, __shfl_xor_sync(0xffffffffu, mx1, 2));
            float nm0 = fmaxf(m0, mx0);
            float nm1 = fmaxf(m1, mx1);
            float cf0 = __expf(m0 - nm0);
            float cf1 = __expf(m1 - nm1);
            m0 = nm0;
            m1 = nm1;

            const int g  = lane >> 2;
            const int t2 = (lane & 3) * 2;
            const int prow0 = warp * 16 + g;
            const int prow1 = prow0 + 8;
            float ps0 = 0.f, ps1 = 0.f;
#pragma unroll
            for (int nt = 0; nt < 8; nt++) {
                float p0 = __expf(sc[nt][0] - nm0);
                float p1 = __expf(sc[nt][1] - nm0);
                float p2 = __expf(sc[nt][2] - nm1);
                float p3 = __expf(sc[nt][3] - nm1);
                ps0 += p0 + p1;
                ps1 += p2 + p3;
                __half2 h01 = __floats2half2_rn(p0, p1);
                __half2 h23 = __floats2half2_rn(p2, p3);
                int uu0 = nt ^ (prow0 & 7);
                int uu1 = nt ^ (prow1 & 7);
                *(__half2*)(smc + ASPS + prow0 * 128 + uu0 * 16 + t2 * 2) = h01;
                *(__half2*)(smc + ASPS + prow1 * 128 + uu1 * 16 + t2 * 2) = h23;
            }
            ps0 += __shfl_xor_sync(0xffffffffu, ps0, 1);
            ps0 += __shfl_xor_sync(0xffffffffu, ps0, 2);
            ps1 += __shfl_xor_sync(0xffffffffu, ps1, 1);
            ps1 += __shfl_xor_sync(0xffffffffu, ps1, 2);
            l0 = l0 * cf0 + ps0;
            l1 = l1 * cf1 + ps1;
#pragma unroll
            for (int nt = 0; nt < 16; nt++) {
                oacc[nt][0] *= cf0;
                oacc[nt][1] *= cf0;
                oacc[nt][2] *= cf1;
                oacc[nt][3] *= cf1;
            }
        }
        __syncwarp();

#pragma unroll
        for (int k2 = 0; k2 < 4; k2++) {
            uint32_t af[4];
            {
                int u  = 2 * k2 + gsel;
                int uu = u ^ (qrow & 7);
                ldsm4(af[0], af[1], af[2], af[3],
                      su + ASPS + (uint32_t)(qrow * 128 + uu * 16));
            }
            uint32_t vf[8][4];
#pragma unroll
            for (int jp = 0; jp < 8; jp++) {
                int row = k2 * 16 + frow;
                int u   = 2 * jp + gsel;
                int uu  = (u & 8) | ((u & 7) ^ (row & 7));
                ldsm4t(vf[jp][0], vf[jp][1], vf[jp][2], vf[jp][3],
                       Vbase + (uint32_t)(row * 256 + uu * 16));
            }
#pragma unroll
            for (int jp = 0; jp < 8; jp++) {
                mma_f16(oacc[jp * 2],     af, vf[jp][0], vf[jp][1]);
                mma_f16(oacc[jp * 2 + 1], af, vf[jp][2], vf[jp][3]);
            }
        }
        __syncthreads();

        if (kt + 2 < 32) {
            load_kv(kt + 2, bb);
        }
        cp_commit();
    }

    {
        float r0 = 1.f / l0;
        float r1 = 1.f / l1;
        const int g  = lane >> 2;
        const int t2 = (lane & 3) * 2;
        int row0 = q0 + warp * 16 + g;
        __half* op0 = O + (long)(b * SEQ + row0) * DIM + h * HD;
        __half* op1 = op0 + (long)8 * DIM;
#pragma unroll
        for (int nt = 0; nt < 16; nt++) {
            *(__half2*)(op0 + nt * 8 + t2) =
                __floats2half2_rn(oacc[nt][0] * r0, oacc[nt][1] * r0);
            *(__half2*)(op1 + nt * 8 + t2) =
                __floats2half2_rn(oacc[nt][2] * r1, oacc[nt][3] * r1);
        }
    }
}

// ==================================================================
// Launch
// ==================================================================
extern "C" void kernel_launch(void* const* d_in, const int* in_sizes, int n_in,
                              void* d_out, int out_size)
{
    (void)in_sizes;
    (void)n_in;
    (void)out_size;
    const float* x  = (const float*)d_in[0];
    const float* wq = (const float*)d_in[1];
    const float* wk = (const float*)d_in[2];
    const float* wv = (const float*)d_in[3];
    const float* wo = (const float*)d_in[4];
    const int*   sp = (const int*)d_in[5];
    float* out = (float*)d_out;

    float* q;
    float* k;
    __half* hx;
    __half* hwq;
    __half* hwk;
    __half* hwv;
    __half* hwo;
    __half* hq;
    __half* hkb;
    __half* hvb;
    __half* ho;
    float* invf;
    cudaGetSymbolAddress((void**)&q,    g_q);
    cudaGetSymbolAddress((void**)&k,    g_k);
    cudaGetSymbolAddress((void**)&hx,   g_hx);
    cudaGetSymbolAddress((void**)&hwq,  g_hwq);
    cudaGetSymbolAddress((void**)&hwk,  g_hwk);
    cudaGetSymbolAddress((void**)&hwv,  g_hwv);
    cudaGetSymbolAddress((void**)&hwo,  g_hwo);
    cudaGetSymbolAddress((void**)&hq,   g_hq);
    cudaGetSymbolAddress((void**)&hkb,  g_hk);
    cudaGetSymbolAddress((void**)&hvb,  g_hv);
    cudaGetSymbolAddress((void**)&ho,   g_ho);
    cudaGetSymbolAddress((void**)&invf, g_invf);

    cudaFuncSetAttribute(gemm_qkv,
                         cudaFuncAttributeMaxDynamicSharedMemorySize, HGEMM_SMEM);
    cudaFuncSetAttribute(gemm_wo,
                         cudaFuncAttributeMaxDynamicSharedMemorySize, HGEMM_SMEM);
    cudaFuncSetAttribute(attn_f16_kernel,
                         cudaFuncAttributeMaxDynamicSharedMemorySize, ATTN_SMEM);

    invf_kernel<<<1, 64>>>(invf);

    {
        int n4x  = MROWS * DIM / 4;
        int n4q  = DIM * DIM / 4;
        int n4kv = KV_DIM * DIM / 4;
        int total = n4x + n4q + 2 * n4kv + n4q;
        to_half5_kernel<<<(total + 255) / 256, 256>>>(
            x, hx, n4x, wq, hwq, n4q, wk, hwk, n4kv, wv, hwv, n4kv, wo, hwo, n4q);
    }

    gemm_qkv<<<1536, 256, HGEMM_SMEM>>>(hx, hwq, hwk, hwv, q, k, hvb);

    rope_both_kernel<<<(MROWS * 64) / 256, 256>>>(q, hq, k, hkb, sp, invf,
                                                  0.08838834764831845f);

    dim3 ga(SEQ / 128, NHQ, BATCH);
    attn_f16_kernel<<<ga, 256, ATTN_SMEM>>>(hq, hkb, hvb, ho);

    dim3 gw(DIM / HBN, MROWS / HBM);
    gemm_wo<<<gw, 256, HGEMM_SMEM>>>(ho, hwo, out, DIM, DIM);
}